// round 1
// baseline (speedup 1.0000x reference)
#include <cuda_runtime.h>
#include <math.h>

#define N_NODES 100000
#define N_EDGES 1600000
#define D 64

// ---------------- scratch (static device globals; no allocations) ----------
__device__ float g_a1[N_NODES];
__device__ float g_a2[N_NODES];
__device__ int   g_cnt[N_NODES];
__device__ int   g_off[N_NODES];
__device__ int   g_cur[N_NODES];
__device__ int   g_csr_src[N_EDGES];
__device__ float g_csr_rf[N_EDGES];
__device__ float g_csr_sc[N_EDGES];
__device__ float g_agg1[N_NODES * D];
__device__ float g_agg2[N_NODES * D];
__device__ float g_h[N_NODES * D];
__device__ float g_t[N_NODES * 2 * D];

__device__ __forceinline__ float gelu_exact(float v) {
    return 0.5f * v * (1.0f + erff(v * 0.70710678118654752440f));
}

// LN over 64 values held 2-per-lane, then scale/shift and store.
__device__ __forceinline__ void ln_write(float v0, float v1, int node, int l,
                                         const float* __restrict__ g,
                                         const float* __restrict__ b,
                                         float* __restrict__ dst) {
    float s = v0 + v1, q = v0 * v0 + v1 * v1;
    #pragma unroll
    for (int o = 16; o; o >>= 1) {
        s += __shfl_xor_sync(0xffffffffu, s, o);
        q += __shfl_xor_sync(0xffffffffu, q, o);
    }
    float mu  = s * (1.0f / 64.0f);
    float var = q * (1.0f / 64.0f) - mu * mu;
    float r   = rsqrtf(var + 1e-5f);
    float2 gg = *reinterpret_cast<const float2*>(g + 2 * l);
    float2 bb = *reinterpret_cast<const float2*>(b + 2 * l);
    float2 o2 = make_float2((v0 - mu) * r * gg.x + bb.x,
                            (v1 - mu) * r * gg.y + bb.y);
    *reinterpret_cast<float2*>(dst + node * D + 2 * l) = o2;
}

// ---------------- K1: per-node attention dots + zero counters ---------------
__global__ void k1_nodeprep(const float* __restrict__ x, const float* __restrict__ attw) {
    int w = (blockIdx.x * blockDim.x + threadIdx.x) >> 5;
    int l = threadIdx.x & 31;
    if (w >= N_NODES) return;
    const float* xr = x + w * D;
    float v0 = xr[l], v1 = xr[l + 32];
    float s1 = v0 * attw[l]     + v1 * attw[l + 32];
    float s2 = v0 * attw[D + l] + v1 * attw[D + l + 32];
    #pragma unroll
    for (int o = 16; o; o >>= 1) {
        s1 += __shfl_xor_sync(0xffffffffu, s1, o);
        s2 += __shfl_xor_sync(0xffffffffu, s2, o);
    }
    if (l == 0) { g_a1[w] = s1; g_a2[w] = s2; g_cnt[w] = 0; }
}

// ---------------- K2: histogram of destination degrees ----------------------
__global__ void k2_hist(const int* __restrict__ ei) {
    int e = blockIdx.x * blockDim.x + threadIdx.x;
    if (e >= N_EDGES) return;
    atomicAdd(&g_cnt[ei[N_EDGES + e]], 1);
}

// ---------------- K3: single-block exclusive scan ---------------------------
__global__ void k3_scan() {
    __shared__ int sb[1024];
    int t = threadIdx.x;
    const int CH = (N_NODES + 1023) / 1024;
    int b0 = t * CH;
    int b1 = b0 + CH; if (b1 > N_NODES) b1 = N_NODES;
    int s = 0;
    for (int i = b0; i < b1; i++) s += g_cnt[i];
    sb[t] = s;
    __syncthreads();
    for (int o = 1; o < 1024; o <<= 1) {
        int u = (t >= o) ? sb[t - o] : 0;
        __syncthreads();
        sb[t] += u;
        __syncthreads();
    }
    int run = sb[t] - s;  // exclusive prefix of this thread's chunk
    for (int i = b0; i < b1; i++) {
        g_off[i] = run;
        g_cur[i] = run;
        run += g_cnt[i];
    }
}

// ---------------- K4: scatter edges into CSR (src, rf, score) ---------------
__global__ void k4_scatter(const int* __restrict__ ei, const float* __restrict__ rf) {
    int e = blockIdx.x * blockDim.x + threadIdx.x;
    if (e >= N_EDGES) return;
    int s = ei[e], d = ei[N_EDGES + e];
    int pos = atomicAdd(&g_cur[d], 1);
    g_csr_src[pos] = s;
    g_csr_rf[pos]  = rf[e];
    g_csr_sc[pos]  = g_a1[s] + g_a2[d];
}

// ---------------- K5: warp-per-node softmax + weighted gather ---------------
__global__ void k5_agg(const float* __restrict__ x, const float* __restrict__ cf) {
    int w = (blockIdx.x * blockDim.x + threadIdx.x) >> 5;
    int l = threadIdx.x & 31;
    if (w >= N_NODES) return;
    int beg = g_off[w], cnt = g_cnt[w];
    float alpha = 1.0f / (1.0f + __expf(-cf[0]));
    float m = -1e30f;
    for (int i = l; i < cnt; i += 32) m = fmaxf(m, g_csr_sc[beg + i]);
    #pragma unroll
    for (int o = 16; o; o >>= 1) m = fmaxf(m, __shfl_xor_sync(0xffffffffu, m, o));
    float den = 0.0f;
    for (int i = l; i < cnt; i += 32) den += __expf(g_csr_sc[beg + i] - m);
    #pragma unroll
    for (int o = 16; o; o >>= 1) den += __shfl_xor_sync(0xffffffffu, den, o);
    float inv = cnt ? (1.0f / den) : 0.0f;
    float a1x = 0.f, a1y = 0.f, a2x = 0.f, a2y = 0.f;
    for (int i = 0; i < cnt; i++) {
        int   src = g_csr_src[beg + i];
        float wgt = __expf(g_csr_sc[beg + i] - m) * inv;
        float s1  = wgt * alpha * g_csr_rf[beg + i];
        float s2  = wgt * (1.0f - alpha);
        float2 xv = *reinterpret_cast<const float2*>(x + src * D + 2 * l);
        a1x += s1 * xv.x; a1y += s1 * xv.y;
        a2x += s2 * xv.x; a2y += s2 * xv.y;
    }
    *reinterpret_cast<float2*>(g_agg1 + w * D + 2 * l) = make_float2(a1x, a1y);
    *reinterpret_cast<float2*>(g_agg2 + w * D + 2 * l) = make_float2(a2x, a2y);
}

// ---------------- K6: out = agg1@Wp^T + agg2@Wn^T; gelu; +x; LN1 -> g_h -----
#define PBLK 592
__global__ void k6_gemm_ln1(const float* __restrict__ x,
                            const float* __restrict__ Wp,
                            const float* __restrict__ Wn,
                            const float* __restrict__ g1,
                            const float* __restrict__ b1) {
    __shared__ float sWp[64 * 66];
    __shared__ float sWn[64 * 66];
    __shared__ float sRow[8][4][64];
    int tid = threadIdx.x;
    for (int i = tid; i < 4096; i += 256) {
        int d = i >> 6, k = i & 63;
        sWp[k * 66 + d] = Wp[i];
        sWn[k * 66 + d] = Wn[i];
    }
    __syncthreads();
    int wid = tid >> 5, l = tid & 31;
    const int NPAIR = N_NODES / 2;
    for (int p = blockIdx.x * 8 + wid; p < NPAIR; p += PBLK * 8) {
        int n0 = 2 * p, n1 = 2 * p + 1;
        __syncwarp();
        float2 r;
        r = *reinterpret_cast<const float2*>(g_agg1 + n0 * D + 2 * l);
        *reinterpret_cast<float2*>(&sRow[wid][0][2 * l]) = r;
        r = *reinterpret_cast<const float2*>(g_agg2 + n0 * D + 2 * l);
        *reinterpret_cast<float2*>(&sRow[wid][1][2 * l]) = r;
        r = *reinterpret_cast<const float2*>(g_agg1 + n1 * D + 2 * l);
        *reinterpret_cast<float2*>(&sRow[wid][2][2 * l]) = r;
        r = *reinterpret_cast<const float2*>(g_agg2 + n1 * D + 2 * l);
        *reinterpret_cast<float2*>(&sRow[wid][3][2 * l]) = r;
        __syncwarp();
        float o0x = 0.f, o0y = 0.f, o1x = 0.f, o1y = 0.f;
        #pragma unroll 8
        for (int k = 0; k < 64; k++) {
            float a10 = sRow[wid][0][k], a20 = sRow[wid][1][k];
            float a11 = sRow[wid][2][k], a21 = sRow[wid][3][k];
            float2 wp = *reinterpret_cast<const float2*>(&sWp[k * 66 + 2 * l]);
            float2 wn = *reinterpret_cast<const float2*>(&sWn[k * 66 + 2 * l]);
            o0x += a10 * wp.x + a20 * wn.x;
            o0y += a10 * wp.y + a20 * wn.y;
            o1x += a11 * wp.x + a21 * wn.x;
            o1y += a11 * wp.y + a21 * wn.y;
        }
        {
            float2 xv = *reinterpret_cast<const float2*>(x + n0 * D + 2 * l);
            float h0 = gelu_exact(o0x) + xv.x;
            float h1 = gelu_exact(o0y) + xv.y;
            ln_write(h0, h1, n0, l, g1, b1, g_h);
        }
        {
            float2 xv = *reinterpret_cast<const float2*>(x + n1 * D + 2 * l);
            float h0 = gelu_exact(o1x) + xv.x;
            float h1 = gelu_exact(o1y) + xv.y;
            ln_write(h0, h1, n1, l, g1, b1, g_h);
        }
    }
}

// ---------------- K7a: t = gelu(h @ W1^T + b1) -> g_t -----------------------
__global__ void k7a_mlp1(const float* __restrict__ W1, const float* __restrict__ B1) {
    __shared__ float sW1[64 * 132];
    __shared__ float sB1[128];
    __shared__ float sH[8][2][64];
    int tid = threadIdx.x;
    for (int i = tid; i < 8192; i += 256) {
        int j = i >> 6, k = i & 63;
        sW1[k * 132 + j] = W1[i];
    }
    for (int i = tid; i < 128; i += 256) sB1[i] = B1[i];
    __syncthreads();
    int wid = tid >> 5, l = tid & 31;
    const int NPAIR = N_NODES / 2;
    for (int p = blockIdx.x * 8 + wid; p < NPAIR; p += PBLK * 8) {
        int n0 = 2 * p, n1 = 2 * p + 1;
        __syncwarp();
        float2 r;
        r = *reinterpret_cast<const float2*>(g_h + n0 * D + 2 * l);
        *reinterpret_cast<float2*>(&sH[wid][0][2 * l]) = r;
        r = *reinterpret_cast<const float2*>(g_h + n1 * D + 2 * l);
        *reinterpret_cast<float2*>(&sH[wid][1][2 * l]) = r;
        __syncwarp();
        float4 a0 = make_float4(0.f, 0.f, 0.f, 0.f);
        float4 a1 = make_float4(0.f, 0.f, 0.f, 0.f);
        #pragma unroll 8
        for (int k = 0; k < 64; k++) {
            float h0 = sH[wid][0][k], h1 = sH[wid][1][k];
            float4 w = *reinterpret_cast<const float4*>(&sW1[k * 132 + 4 * l]);
            a0.x += h0 * w.x; a0.y += h0 * w.y; a0.z += h0 * w.z; a0.w += h0 * w.w;
            a1.x += h1 * w.x; a1.y += h1 * w.y; a1.z += h1 * w.z; a1.w += h1 * w.w;
        }
        float4 bb = *reinterpret_cast<const float4*>(&sB1[4 * l]);
        float4 t0, t1;
        t0.x = gelu_exact(a0.x + bb.x); t0.y = gelu_exact(a0.y + bb.y);
        t0.z = gelu_exact(a0.z + bb.z); t0.w = gelu_exact(a0.w + bb.w);
        t1.x = gelu_exact(a1.x + bb.x); t1.y = gelu_exact(a1.y + bb.y);
        t1.z = gelu_exact(a1.z + bb.z); t1.w = gelu_exact(a1.w + bb.w);
        *reinterpret_cast<float4*>(g_t + n0 * 128 + 4 * l) = t0;
        *reinterpret_cast<float4*>(g_t + n1 * 128 + 4 * l) = t1;
    }
}

// ---------------- K7b: out = LN2(t @ W2^T + b2 + h) -------------------------
__global__ void k7b_mlp2(float* __restrict__ out,
                         const float* __restrict__ W2, const float* __restrict__ B2,
                         const float* __restrict__ g2, const float* __restrict__ b2ln) {
    __shared__ float sW2[128 * 66];
    __shared__ float sB2[64];
    __shared__ float sT[8][2][128];
    int tid = threadIdx.x;
    for (int i = tid; i < 8192; i += 256) {
        int d = i >> 7, k = i & 127;
        sW2[k * 66 + d] = W2[i];
    }
    for (int i = tid; i < 64; i += 256) sB2[i] = B2[i];
    __syncthreads();
    int wid = tid >> 5, l = tid & 31;
    const int NPAIR = N_NODES / 2;
    for (int p = blockIdx.x * 8 + wid; p < NPAIR; p += PBLK * 8) {
        int n0 = 2 * p, n1 = 2 * p + 1;
        __syncwarp();
        float4 tv;
        tv = *reinterpret_cast<const float4*>(g_t + n0 * 128 + 4 * l);
        *reinterpret_cast<float4*>(&sT[wid][0][4 * l]) = tv;
        tv = *reinterpret_cast<const float4*>(g_t + n1 * 128 + 4 * l);
        *reinterpret_cast<float4*>(&sT[wid][1][4 * l]) = tv;
        __syncwarp();
        float o0x = 0.f, o0y = 0.f, o1x = 0.f, o1y = 0.f;
        #pragma unroll 8
        for (int k = 0; k < 128; k++) {
            float t0 = sT[wid][0][k], t1 = sT[wid][1][k];
            float2 w = *reinterpret_cast<const float2*>(&sW2[k * 66 + 2 * l]);
            o0x += t0 * w.x; o0y += t0 * w.y;
            o1x += t1 * w.x; o1y += t1 * w.y;
        }
        float2 bb = *reinterpret_cast<const float2*>(&sB2[2 * l]);
        {
            float2 hr = *reinterpret_cast<const float2*>(g_h + n0 * D + 2 * l);
            ln_write(o0x + bb.x + hr.x, o0y + bb.y + hr.y, n0, l, g2, b2ln, out);
        }
        {
            float2 hr = *reinterpret_cast<const float2*>(g_h + n1 * D + 2 * l);
            ln_write(o1x + bb.x + hr.x, o1y + bb.y + hr.y, n1, l, g2, b2ln, out);
        }
    }
}

// ---------------- launcher --------------------------------------------------
extern "C" void kernel_launch(void* const* d_in, const int* in_sizes, int n_in,
                              void* d_out, int out_size) {
    (void)in_sizes; (void)n_in; (void)out_size;
    const float* x    = (const float*)d_in[0];
    const int*   ei   = (const int*)  d_in[1];
    const float* rf   = (const float*)d_in[2];
    const float* Wp   = (const float*)d_in[3];
    const float* Wn   = (const float*)d_in[4];
    const float* attw = (const float*)d_in[5];
    const float* cf   = (const float*)d_in[6];
    const float* W1   = (const float*)d_in[7];
    const float* B1   = (const float*)d_in[8];
    const float* W2   = (const float*)d_in[9];
    const float* B2   = (const float*)d_in[10];
    const float* g1   = (const float*)d_in[11];
    const float* b1   = (const float*)d_in[12];
    const float* g2   = (const float*)d_in[13];
    const float* b2   = (const float*)d_in[14];
    float* out = (float*)d_out;

    k1_nodeprep<<<N_NODES / 8, 256>>>(x, attw);
    k2_hist<<<N_EDGES / 256, 256>>>(ei);
    k3_scan<<<1, 1024>>>();
    k4_scatter<<<N_EDGES / 256, 256>>>(ei, rf);
    k5_agg<<<N_NODES / 8, 256>>>(x, cf);
    k6_gemm_ln1<<<PBLK, 256>>>(x, Wp, Wn, g1, b1);
    k7a_mlp1<<<PBLK, 256>>>(W1, B1);
    k7b_mlp2<<<PBLK, 256>>>(out, W2, B2, g2, b2);
}

// round 3
// speedup vs baseline: 1.0612x; 1.0612x over previous
#include <cuda_runtime.h>
#include <math.h>

#define N_NODES 100000
#define N_EDGES 1600000
#define D 64
#define NSTRIPS 6250            // 100000 / 16

// ---------------- scratch (static device globals; no allocations) ----------
__device__ float  g_a1[N_NODES];
__device__ float  g_a2[N_NODES];
__device__ int    g_cnt[N_NODES];
__device__ int    g_off[N_NODES];
__device__ int    g_cur[N_NODES];
__device__ float4 g_csr[N_EDGES];            // (src_as_int, rf, score, pad)
__device__ float  g_agg[N_NODES * 128];      // cols 0..63: s1-weighted, 64..127: s2-weighted
__device__ float  g_h[N_NODES * D];
__device__ float  g_t[N_NODES * 2 * D];

__device__ __forceinline__ float gelu_exact(float v) {
    return 0.5f * v * (1.0f + erff(v * 0.70710678118654752440f));
}

__device__ __forceinline__ unsigned f2tf(float f) {
    unsigned u;
    asm("cvt.rna.tf32.f32 %0, %1;" : "=r"(u) : "f"(f));
    return u;
}

__device__ __forceinline__ void mma_tf32(float c[4],
                                         unsigned a0, unsigned a1, unsigned a2, unsigned a3,
                                         unsigned b0, unsigned b1) {
    asm("mma.sync.aligned.m16n8k8.row.col.f32.tf32.tf32.f32 "
        "{%0,%1,%2,%3},{%4,%5,%6,%7},{%8,%9},{%0,%1,%2,%3};"
        : "+f"(c[0]), "+f"(c[1]), "+f"(c[2]), "+f"(c[3])
        : "r"(a0), "r"(a1), "r"(a2), "r"(a3), "r"(b0), "r"(b1));
}

// 3-term split-tf32 accumulate: c += A*B with ~fp32 accuracy
__device__ __forceinline__ void mma3(float c[4],
                                     unsigned ah0, unsigned ah1, unsigned ah2, unsigned ah3,
                                     unsigned al0, unsigned al1, unsigned al2, unsigned al3,
                                     float b0w, float b1w) {
    unsigned bh0 = f2tf(b0w), bh1 = f2tf(b1w);
    unsigned bl0 = f2tf(b0w - __uint_as_float(bh0));
    unsigned bl1 = f2tf(b1w - __uint_as_float(bh1));
    mma_tf32(c, ah0, ah1, ah2, ah3, bh0, bh1);
    mma_tf32(c, ah0, ah1, ah2, ah3, bl0, bl1);
    mma_tf32(c, al0, al1, al2, al3, bh0, bh1);
}

// ---------------- K1: per-node attention dots + zero counters ---------------
__global__ void k1_nodeprep(const float* __restrict__ x, const float* __restrict__ attw) {
    int w = (blockIdx.x * blockDim.x + threadIdx.x) >> 5;
    int l = threadIdx.x & 31;
    if (w >= N_NODES) return;
    const float* xr = x + w * D;
    float v0 = xr[l], v1 = xr[l + 32];
    float s1 = v0 * attw[l]     + v1 * attw[l + 32];
    float s2 = v0 * attw[D + l] + v1 * attw[D + l + 32];
    #pragma unroll
    for (int o = 16; o; o >>= 1) {
        s1 += __shfl_xor_sync(0xffffffffu, s1, o);
        s2 += __shfl_xor_sync(0xffffffffu, s2, o);
    }
    if (l == 0) { g_a1[w] = s1; g_a2[w] = s2; g_cnt[w] = 0; }
}

// ---------------- K2: histogram of destination degrees ----------------------
__global__ void k2_hist(const int* __restrict__ ei) {
    int e = blockIdx.x * blockDim.x + threadIdx.x;
    if (e >= N_EDGES) return;
    atomicAdd(&g_cnt[ei[N_EDGES + e]], 1);
}

// ---------------- K3: single-block exclusive scan ---------------------------
__global__ void k3_scan() {
    __shared__ int sb[1024];
    int t = threadIdx.x;
    const int CH = (N_NODES + 1023) / 1024;
    int b0 = t * CH;
    int b1 = b0 + CH; if (b1 > N_NODES) b1 = N_NODES;
    int s = 0;
    for (int i = b0; i < b1; i++) s += g_cnt[i];
    sb[t] = s;
    __syncthreads();
    for (int o = 1; o < 1024; o <<= 1) {
        int u = (t >= o) ? sb[t - o] : 0;
        __syncthreads();
        sb[t] += u;
        __syncthreads();
    }
    int run = sb[t] - s;
    for (int i = b0; i < b1; i++) {
        g_off[i] = run;
        g_cur[i] = run;
        run += g_cnt[i];
    }
}

// ---------------- K4: scatter edges into CSR (packed float4) ----------------
__global__ void k4_scatter(const int* __restrict__ ei, const float* __restrict__ rf) {
    int e = blockIdx.x * blockDim.x + threadIdx.x;
    if (e >= N_EDGES) return;
    int s = ei[e], d = ei[N_EDGES + e];
    int pos = atomicAdd(&g_cur[d], 1);
    g_csr[pos] = make_float4(__int_as_float(s), rf[e], g_a1[s] + g_a2[d], 0.0f);
}

// ---------------- K5: warp-per-node softmax + weighted gather ---------------
__global__ void k5_agg(const float* __restrict__ x, const float* __restrict__ cf) {
    int w = (blockIdx.x * blockDim.x + threadIdx.x) >> 5;
    int l = threadIdx.x & 31;
    if (w >= N_NODES) return;
    int beg = g_off[w], cnt = g_cnt[w];
    float alpha = 1.0f / (1.0f + __expf(-cf[0]));
    float m = -1e30f;
    for (int i = l; i < cnt; i += 32) m = fmaxf(m, g_csr[beg + i].z);
    #pragma unroll
    for (int o = 16; o; o >>= 1) m = fmaxf(m, __shfl_xor_sync(0xffffffffu, m, o));
    float den = 0.0f;
    for (int i = l; i < cnt; i += 32) den += __expf(g_csr[beg + i].z - m);
    #pragma unroll
    for (int o = 16; o; o >>= 1) den += __shfl_xor_sync(0xffffffffu, den, o);
    float inv = cnt ? (1.0f / den) : 0.0f;
    float a1x = 0.f, a1y = 0.f, a2x = 0.f, a2y = 0.f;
    for (int i = 0; i < cnt; i++) {
        float4 ed = g_csr[beg + i];
        int   src = __float_as_int(ed.x);
        float wgt = __expf(ed.z - m) * inv;
        float s1  = wgt * alpha * ed.y;
        float s2  = wgt * (1.0f - alpha);
        float2 xv = *reinterpret_cast<const float2*>(x + src * D + 2 * l);
        a1x += s1 * xv.x; a1y += s1 * xv.y;
        a2x += s2 * xv.x; a2y += s2 * xv.y;
    }
    *reinterpret_cast<float2*>(g_agg + w * 128 + 2 * l)      = make_float2(a1x, a1y);
    *reinterpret_cast<float2*>(g_agg + w * 128 + 64 + 2 * l) = make_float2(a2x, a2y);
}

// ---------------- K6: h = LN1(gelu(agg @ [Wp;Wn]^T) + x)  (tf32 MMA) --------
__global__ void __launch_bounds__(256) k6_gemm_ln1(
        const float* __restrict__ x,
        const float* __restrict__ Wp, const float* __restrict__ Wn,
        const float* __restrict__ g1, const float* __restrict__ b1) {
    __shared__ float sB[128 * 64];           // B[k][n]: k<64 -> Wp[n][k], k>=64 -> Wn[n][k-64]
    int tid = threadIdx.x;
    for (int i = tid; i < 8192; i += 256) {
        int n = i >> 7, k = i & 127;
        sB[k * 64 + n] = (k < 64) ? Wp[n * 64 + k] : Wn[n * 64 + (k - 64)];
    }
    __syncthreads();
    int wid = tid >> 5, lane = tid & 31;
    int gid = lane >> 2, tig = lane & 3;
    int strip = blockIdx.x * 8 + wid;
    if (strip >= NSTRIPS) return;
    int r0 = strip * 16 + gid, r1 = r0 + 8;

    float c[8][4];
    #pragma unroll
    for (int nt = 0; nt < 8; nt++)
        c[nt][0] = c[nt][1] = c[nt][2] = c[nt][3] = 0.f;

    #pragma unroll 2
    for (int kk = 0; kk < 16; kk++) {
        int kb = kk * 8;
        float a00 = g_agg[r0 * 128 + kb + tig];
        float a10 = g_agg[r1 * 128 + kb + tig];
        float a01 = g_agg[r0 * 128 + kb + tig + 4];
        float a11 = g_agg[r1 * 128 + kb + tig + 4];
        unsigned ah0 = f2tf(a00), ah1 = f2tf(a10), ah2 = f2tf(a01), ah3 = f2tf(a11);
        unsigned al0 = f2tf(a00 - __uint_as_float(ah0));
        unsigned al1 = f2tf(a10 - __uint_as_float(ah1));
        unsigned al2 = f2tf(a01 - __uint_as_float(ah2));
        unsigned al3 = f2tf(a11 - __uint_as_float(ah3));
        const float* br0 = &sB[(kb + tig) * 64];
        const float* br1 = &sB[(kb + tig + 4) * 64];
        #pragma unroll
        for (int nt = 0; nt < 8; nt++) {
            float b0w = br0[nt * 8 + gid];
            float b1w = br1[nt * 8 + gid];
            mma3(c[nt], ah0, ah1, ah2, ah3, al0, al1, al2, al3, b0w, b1w);
        }
    }
    // epilogue: gelu + residual + LN1
    float s0 = 0.f, q0 = 0.f, s1 = 0.f, q1 = 0.f;
    #pragma unroll
    for (int nt = 0; nt < 8; nt++) {
        int col = nt * 8 + 2 * tig;
        float2 xv0 = *reinterpret_cast<const float2*>(x + r0 * D + col);
        float2 xv1 = *reinterpret_cast<const float2*>(x + r1 * D + col);
        c[nt][0] = gelu_exact(c[nt][0]) + xv0.x;
        c[nt][1] = gelu_exact(c[nt][1]) + xv0.y;
        c[nt][2] = gelu_exact(c[nt][2]) + xv1.x;
        c[nt][3] = gelu_exact(c[nt][3]) + xv1.y;
        s0 += c[nt][0] + c[nt][1]; q0 += c[nt][0] * c[nt][0] + c[nt][1] * c[nt][1];
        s1 += c[nt][2] + c[nt][3]; q1 += c[nt][2] * c[nt][2] + c[nt][3] * c[nt][3];
    }
    #pragma unroll
    for (int o = 1; o <= 2; o <<= 1) {
        s0 += __shfl_xor_sync(0xffffffffu, s0, o);
        q0 += __shfl_xor_sync(0xffffffffu, q0, o);
        s1 += __shfl_xor_sync(0xffffffffu, s1, o);
        q1 += __shfl_xor_sync(0xffffffffu, q1, o);
    }
    float mu0 = s0 * (1.0f / 64.0f), var0 = q0 * (1.0f / 64.0f) - mu0 * mu0;
    float mu1 = s1 * (1.0f / 64.0f), var1 = q1 * (1.0f / 64.0f) - mu1 * mu1;
    float rs0 = rsqrtf(var0 + 1e-5f), rs1 = rsqrtf(var1 + 1e-5f);
    #pragma unroll
    for (int nt = 0; nt < 8; nt++) {
        int col = nt * 8 + 2 * tig;
        float2 gg = *reinterpret_cast<const float2*>(g1 + col);
        float2 bb = *reinterpret_cast<const float2*>(b1 + col);
        float2 o0 = make_float2((c[nt][0] - mu0) * rs0 * gg.x + bb.x,
                                (c[nt][1] - mu0) * rs0 * gg.y + bb.y);
        float2 o1 = make_float2((c[nt][2] - mu1) * rs1 * gg.x + bb.x,
                                (c[nt][3] - mu1) * rs1 * gg.y + bb.y);
        *reinterpret_cast<float2*>(g_h + r0 * D + col) = o0;
        *reinterpret_cast<float2*>(g_h + r1 * D + col) = o1;
    }
}

// ---------------- K7a: t = gelu(h @ W1^T + b1)   (tf32 MMA) -----------------
__global__ void __launch_bounds__(256) k7a_mlp1(
        const float* __restrict__ W1, const float* __restrict__ B1) {
    __shared__ float sB[64 * 128];           // B[k][j] = W1[j][k]
    int tid = threadIdx.x;
    for (int i = tid; i < 8192; i += 256) {
        int j = i >> 6, k = i & 63;
        sB[k * 128 + j] = W1[i];
    }
    __syncthreads();
    int wid = tid >> 5, lane = tid & 31;
    int gid = lane >> 2, tig = lane & 3;
    int strip = blockIdx.x * 8 + wid;
    if (strip >= NSTRIPS) return;
    int r0 = strip * 16 + gid, r1 = r0 + 8;

    float c[16][4];
    #pragma unroll
    for (int nt = 0; nt < 16; nt++)
        c[nt][0] = c[nt][1] = c[nt][2] = c[nt][3] = 0.f;

    #pragma unroll 2
    for (int kk = 0; kk < 8; kk++) {
        int kb = kk * 8;
        float a00 = g_h[r0 * D + kb + tig];
        float a10 = g_h[r1 * D + kb + tig];
        float a01 = g_h[r0 * D + kb + tig + 4];
        float a11 = g_h[r1 * D + kb + tig + 4];
        unsigned ah0 = f2tf(a00), ah1 = f2tf(a10), ah2 = f2tf(a01), ah3 = f2tf(a11);
        unsigned al0 = f2tf(a00 - __uint_as_float(ah0));
        unsigned al1 = f2tf(a10 - __uint_as_float(ah1));
        unsigned al2 = f2tf(a01 - __uint_as_float(ah2));
        unsigned al3 = f2tf(a11 - __uint_as_float(ah3));
        const float* br0 = &sB[(kb + tig) * 128];
        const float* br1 = &sB[(kb + tig + 4) * 128];
        #pragma unroll
        for (int nt = 0; nt < 16; nt++) {
            float b0w = br0[nt * 8 + gid];
            float b1w = br1[nt * 8 + gid];
            mma3(c[nt], ah0, ah1, ah2, ah3, al0, al1, al2, al3, b0w, b1w);
        }
    }
    #pragma unroll
    for (int nt = 0; nt < 16; nt++) {
        int col = nt * 8 + 2 * tig;
        float2 bb = *reinterpret_cast<const float2*>(B1 + col);
        float2 t0 = make_float2(gelu_exact(c[nt][0] + bb.x), gelu_exact(c[nt][1] + bb.y));
        float2 t1 = make_float2(gelu_exact(c[nt][2] + bb.x), gelu_exact(c[nt][3] + bb.y));
        *reinterpret_cast<float2*>(g_t + r0 * 128 + col) = t0;
        *reinterpret_cast<float2*>(g_t + r1 * 128 + col) = t1;
    }
}

// ---------------- K7b: out = LN2(t @ W2^T + b2 + h)   (tf32 MMA) ------------
__global__ void __launch_bounds__(256) k7b_mlp2(
        float* __restrict__ out,
        const float* __restrict__ W2, const float* __restrict__ B2,
        const float* __restrict__ g2, const float* __restrict__ b2ln) {
    __shared__ float sB[128 * 64];           // B[k][n] = W2[n][k]
    int tid = threadIdx.x;
    for (int i = tid; i < 8192; i += 256) {
        int n = i >> 7, k = i & 127;
        sB[k * 64 + n] = W2[n * 128 + k];
    }
    __syncthreads();
    int wid = tid >> 5, lane = tid & 31;
    int gid = lane >> 2, tig = lane & 3;
    int strip = blockIdx.x * 8 + wid;
    if (strip >= NSTRIPS) return;
    int r0 = strip * 16 + gid, r1 = r0 + 8;

    float c[8][4];
    #pragma unroll
    for (int nt = 0; nt < 8; nt++)
        c[nt][0] = c[nt][1] = c[nt][2] = c[nt][3] = 0.f;

    #pragma unroll 2
    for (int kk = 0; kk < 16; kk++) {
        int kb = kk * 8;
        float a00 = g_t[r0 * 128 + kb + tig];
        float a10 = g_t[r1 * 128 + kb + tig];
        float a01 = g_t[r0 * 128 + kb + tig + 4];
        float a11 = g_t[r1 * 128 + kb + tig + 4];
        unsigned ah0 = f2tf(a00), ah1 = f2tf(a10), ah2 = f2tf(a01), ah3 = f2tf(a11);
        unsigned al0 = f2tf(a00 - __uint_as_float(ah0));
        unsigned al1 = f2tf(a10 - __uint_as_float(ah1));
        unsigned al2 = f2tf(a01 - __uint_as_float(ah2));
        unsigned al3 = f2tf(a11 - __uint_as_float(ah3));
        const float* br0 = &sB[(kb + tig) * 64];
        const float* br1 = &sB[(kb + tig + 4) * 64];
        #pragma unroll
        for (int nt = 0; nt < 8; nt++) {
            float b0w = br0[nt * 8 + gid];
            float b1w = br1[nt * 8 + gid];
            mma3(c[nt], ah0, ah1, ah2, ah3, al0, al1, al2, al3, b0w, b1w);
        }
    }
    // epilogue: bias + residual + LN2
    float s0 = 0.f, q0 = 0.f, s1 = 0.f, q1 = 0.f;
    #pragma unroll
    for (int nt = 0; nt < 8; nt++) {
        int col = nt * 8 + 2 * tig;
        float2 bb = *reinterpret_cast<const float2*>(B2 + col);
        float2 h0 = *reinterpret_cast<const float2*>(g_h + r0 * D + col);
        float2 h1 = *reinterpret_cast<const float2*>(g_h + r1 * D + col);
        c[nt][0] += bb.x + h0.x;
        c[nt][1] += bb.y + h0.y;
        c[nt][2] += bb.x + h1.x;
        c[nt][3] += bb.y + h1.y;
        s0 += c[nt][0] + c[nt][1]; q0 += c[nt][0] * c[nt][0] + c[nt][1] * c[nt][1];
        s1 += c[nt][2] + c[nt][3]; q1 += c[nt][2] * c[nt][2] + c[nt][3] * c[nt][3];
    }
    #pragma unroll
    for (int o = 1; o <= 2; o <<= 1) {
        s0 += __shfl_xor_sync(0xffffffffu, s0, o);
        q0 += __shfl_xor_sync(0xffffffffu, q0, o);
        s1 += __shfl_xor_sync(0xffffffffu, s1, o);
        q1 += __shfl_xor_sync(0xffffffffu, q1, o);
    }
    float mu0 = s0 * (1.0f / 64.0f), var0 = q0 * (1.0f / 64.0f) - mu0 * mu0;
    float mu1 = s1 * (1.0f / 64.0f), var1 = q1 * (1.0f / 64.0f) - mu1 * mu1;
    float rs0 = rsqrtf(var0 + 1e-5f), rs1 = rsqrtf(var1 + 1e-5f);
    #pragma unroll
    for (int nt = 0; nt < 8; nt++) {
        int col = nt * 8 + 2 * tig;
        float2 gg = *reinterpret_cast<const float2*>(g2 + col);
        float2 bb = *reinterpret_cast<const float2*>(b2ln + col);
        float2 o0 = make_float2((c[nt][0] - mu0) * rs0 * gg.x + bb.x,
                                (c[nt][1] - mu0) * rs0 * gg.y + bb.y);
        float2 o1 = make_float2((c[nt][2] - mu1) * rs1 * gg.x + bb.x,
                                (c[nt][3] - mu1) * rs1 * gg.y + bb.y);
        *reinterpret_cast<float2*>(out + r0 * D + col) = o0;
        *reinterpret_cast<float2*>(out + r1 * D + col) = o1;
    }
}

// ---------------- launcher --------------------------------------------------
extern "C" void kernel_launch(void* const* d_in, const int* in_sizes, int n_in,
                              void* d_out, int out_size) {
    (void)in_sizes; (void)n_in; (void)out_size;
    const float* x    = (const float*)d_in[0];
    const int*   ei   = (const int*)  d_in[1];
    const float* rf   = (const float*)d_in[2];
    const float* Wp   = (const float*)d_in[3];
    const float* Wn   = (const float*)d_in[4];
    const float* attw = (const float*)d_in[5];
    const float* cf   = (const float*)d_in[6];
    const float* W1   = (const float*)d_in[7];
    const float* B1   = (const float*)d_in[8];
    const float* W2   = (const float*)d_in[9];
    const float* B2   = (const float*)d_in[10];
    const float* g1   = (const float*)d_in[11];
    const float* b1   = (const float*)d_in[12];
    const float* g2   = (const float*)d_in[13];
    const float* b2   = (const float*)d_in[14];
    float* out = (float*)d_out;

    const int GBLK = (NSTRIPS + 7) / 8;      // 782

    k1_nodeprep<<<N_NODES / 8, 256>>>(x, attw);
    k2_hist<<<N_EDGES / 256, 256>>>(ei);
    k3_scan<<<1, 1024>>>();
    k4_scatter<<<N_EDGES / 256, 256>>>(ei, rf);
    k5_agg<<<N_NODES / 8, 256>>>(x, cf);
    k6_gemm_ln1<<<GBLK, 256>>>(x, Wp, Wn, g1, b1);
    k7a_mlp1<<<GBLK, 256>>>(W1, B1);
    k7b_mlp2<<<GBLK, 256>>>(out, W2, B2, g2, b2);
}

// round 5
// speedup vs baseline: 1.1698x; 1.1023x over previous
#include <cuda_runtime.h>
#include <math.h>

#define N_NODES 100000
#define N_EDGES 1600000
#define D 64
#define NSTRIPS 6250            // 100000 / 16
#define FULLM 0xffffffffu

// ---------------- scratch (static device globals; no allocations) ----------
__device__ float  g_a1[N_NODES];
__device__ float  g_a2[N_NODES];
__device__ int    g_cnt[N_NODES];
__device__ int    g_off[N_NODES];
__device__ int    g_cur[N_NODES];
__device__ float4 g_csr[N_EDGES];            // (src_as_int, rf, score, pad)
__device__ float  g_agg[N_NODES * 128];      // cols 0..63: s1-weighted, 64..127: s2-weighted
__device__ float  g_h[N_NODES * D];
__device__ float  g_t[N_NODES * 2 * D];

__device__ __forceinline__ float gelu_exact(float v) {
    return 0.5f * v * (1.0f + erff(v * 0.70710678118654752440f));
}

__device__ __forceinline__ unsigned f2tf(float f) {
    unsigned u;
    asm("cvt.rna.tf32.f32 %0, %1;" : "=r"(u) : "f"(f));
    return u;
}

__device__ __forceinline__ void mma_tf32(float c[4],
                                         unsigned a0, unsigned a1, unsigned a2, unsigned a3,
                                         unsigned b0, unsigned b1) {
    asm("mma.sync.aligned.m16n8k8.row.col.f32.tf32.tf32.f32 "
        "{%0,%1,%2,%3},{%4,%5,%6,%7},{%8,%9},{%0,%1,%2,%3};"
        : "+f"(c[0]), "+f"(c[1]), "+f"(c[2]), "+f"(c[3])
        : "r"(a0), "r"(a1), "r"(a2), "r"(a3), "r"(b0), "r"(b1));
}

// 3-term split-tf32 accumulate: c += A*B with ~fp32 accuracy
__device__ __forceinline__ void mma3(float c[4],
                                     unsigned ah0, unsigned ah1, unsigned ah2, unsigned ah3,
                                     unsigned al0, unsigned al1, unsigned al2, unsigned al3,
                                     float b0w, float b1w) {
    unsigned bh0 = f2tf(b0w), bh1 = f2tf(b1w);
    unsigned bl0 = f2tf(b0w - __uint_as_float(bh0));
    unsigned bl1 = f2tf(b1w - __uint_as_float(bh1));
    mma_tf32(c, ah0, ah1, ah2, ah3, bh0, bh1);
    mma_tf32(c, ah0, ah1, ah2, ah3, bl0, bl1);
    mma_tf32(c, al0, al1, al2, al3, bh0, bh1);
}

// ---------------- K1: per-node attention dots + zero counters ---------------
__global__ void k1_nodeprep(const float* __restrict__ x, const float* __restrict__ attw) {
    int w = (blockIdx.x * blockDim.x + threadIdx.x) >> 5;
    int l = threadIdx.x & 31;
    if (w >= N_NODES) return;
    const float* xr = x + w * D;
    float v0 = xr[l], v1 = xr[l + 32];
    float s1 = v0 * attw[l]     + v1 * attw[l + 32];
    float s2 = v0 * attw[D + l] + v1 * attw[D + l + 32];
    #pragma unroll
    for (int o = 16; o; o >>= 1) {
        s1 += __shfl_xor_sync(FULLM, s1, o);
        s2 += __shfl_xor_sync(FULLM, s2, o);
    }
    if (l == 0) { g_a1[w] = s1; g_a2[w] = s2; g_cnt[w] = 0; }
}

// ---------------- K2: histogram of destination degrees ----------------------
__global__ void k2_hist(const int* __restrict__ ei) {
    int e = blockIdx.x * blockDim.x + threadIdx.x;
    if (e >= N_EDGES) return;
    atomicAdd(&g_cnt[ei[N_EDGES + e]], 1);
}

// ---------------- K3: single-block exclusive scan (vectorized) --------------
__global__ void k3_scan() {
    __shared__ int sb[1024];
    int t = threadIdx.x;
    const int CH = 100;                       // 1024*100 = 102400 >= N_NODES
    int b0 = t * CH;
    int b1 = b0 + CH; if (b1 > N_NODES) b1 = N_NODES;
    int s = 0;
    if (b0 < N_NODES) {
        const int4* p = reinterpret_cast<const int4*>(&g_cnt[b0]);
        int nv = (b1 - b0) >> 2;
        for (int i = 0; i < nv; i++) {
            int4 v = p[i];
            s += v.x + v.y + v.z + v.w;
        }
        for (int i = b0 + nv * 4; i < b1; i++) s += g_cnt[i];
    }
    sb[t] = s;
    __syncthreads();
    for (int o = 1; o < 1024; o <<= 1) {
        int u = (t >= o) ? sb[t - o] : 0;
        __syncthreads();
        sb[t] += u;
        __syncthreads();
    }
    int run = sb[t] - s;
    for (int i = b0; i < b1; i++) {
        int c = g_cnt[i];
        g_off[i] = run;
        g_cur[i] = run;
        run += c;
    }
}

// ---------------- K4: scatter edges into CSR (packed float4) ----------------
__global__ void k4_scatter(const int* __restrict__ ei, const float* __restrict__ rf) {
    int e = blockIdx.x * blockDim.x + threadIdx.x;
    if (e >= N_EDGES) return;
    int s = ei[e], d = ei[N_EDGES + e];
    int pos = atomicAdd(&g_cur[d], 1);
    g_csr[pos] = make_float4(__int_as_float(s), rf[e], g_a1[s] + g_a2[d], 0.0f);
}

// ---------------- K5: warp-per-node softmax + pipelined gather --------------
__global__ void k5_agg(const float* __restrict__ x, const float* __restrict__ cf) {
    int w = (blockIdx.x * blockDim.x + threadIdx.x) >> 5;
    int l = threadIdx.x & 31;
    if (w >= N_NODES) return;
    int beg = g_off[w], cnt = g_cnt[w];
    float alpha = 1.0f / (1.0f + __expf(-cf[0]));

    // stage first 32 edges lane-parallel (one coalesced 512B segment read)
    float4 ed = make_float4(0.f, 0.f, -1e30f, 0.f);
    if (l < cnt) ed = g_csr[beg + l];

    // segment max
    float m = ed.z;
    for (int i = 32 + l; i < cnt; i += 32) m = fmaxf(m, g_csr[beg + i].z);
    #pragma unroll
    for (int o = 16; o; o >>= 1) m = fmaxf(m, __shfl_xor_sync(FULLM, m, o));

    // segment denom
    float e0 = (l < cnt) ? __expf(ed.z - m) : 0.f;
    float den = e0;
    for (int i = 32 + l; i < cnt; i += 32) den += __expf(g_csr[beg + i].z - m);
    #pragma unroll
    for (int o = 16; o; o >>= 1) den += __shfl_xor_sync(FULLM, den, o);
    float inv = (cnt > 0) ? (1.0f / den) : 0.f;

    // per-lane weights for staged edges
    float w1 = e0 * inv * alpha * ed.y;
    float w2 = e0 * inv * (1.0f - alpha);
    int   sr = __float_as_int(ed.x);

    float a1x = 0.f, a1y = 0.f, a2x = 0.f, a2y = 0.f;
    int n0 = cnt < 32 ? cnt : 32;
    int i = 0;
    // 4-way pipelined: all four x-row loads independent
    for (; i + 4 <= n0; i += 4) {
        int   s0 = __shfl_sync(FULLM, sr, i + 0);
        int   s1 = __shfl_sync(FULLM, sr, i + 1);
        int   s2 = __shfl_sync(FULLM, sr, i + 2);
        int   s3 = __shfl_sync(FULLM, sr, i + 3);
        float p0 = __shfl_sync(FULLM, w1, i + 0), q0 = __shfl_sync(FULLM, w2, i + 0);
        float p1 = __shfl_sync(FULLM, w1, i + 1), q1 = __shfl_sync(FULLM, w2, i + 1);
        float p2 = __shfl_sync(FULLM, w1, i + 2), q2 = __shfl_sync(FULLM, w2, i + 2);
        float p3 = __shfl_sync(FULLM, w1, i + 3), q3 = __shfl_sync(FULLM, w2, i + 3);
        float2 v0 = *reinterpret_cast<const float2*>(x + s0 * D + 2 * l);
        float2 v1 = *reinterpret_cast<const float2*>(x + s1 * D + 2 * l);
        float2 v2 = *reinterpret_cast<const float2*>(x + s2 * D + 2 * l);
        float2 v3 = *reinterpret_cast<const float2*>(x + s3 * D + 2 * l);
        a1x += p0 * v0.x; a1y += p0 * v0.y; a2x += q0 * v0.x; a2y += q0 * v0.y;
        a1x += p1 * v1.x; a1y += p1 * v1.y; a2x += q1 * v1.x; a2y += q1 * v1.y;
        a1x += p2 * v2.x; a1y += p2 * v2.y; a2x += q2 * v2.x; a2y += q2 * v2.y;
        a1x += p3 * v3.x; a1y += p3 * v3.y; a2x += q3 * v3.x; a2y += q3 * v3.y;
    }
    for (; i < n0; i++) {
        int   s0 = __shfl_sync(FULLM, sr, i);
        float p0 = __shfl_sync(FULLM, w1, i), q0 = __shfl_sync(FULLM, w2, i);
        float2 v0 = *reinterpret_cast<const float2*>(x + s0 * D + 2 * l);
        a1x += p0 * v0.x; a1y += p0 * v0.y; a2x += q0 * v0.x; a2y += q0 * v0.y;
    }
    // rare overflow chunks (degree > 32)
    for (int base = 32; base < cnt; base += 32) {
        float4 e2 = make_float4(0.f, 0.f, 0.f, 0.f);
        int k = base + l;
        if (k < cnt) e2 = g_csr[beg + k];
        float ew = (k < cnt) ? __expf(e2.z - m) * inv : 0.f;
        float u1 = ew * alpha * e2.y;
        float u2 = ew * (1.0f - alpha);
        int  s2r = __float_as_int(e2.x);
        int lim = cnt - base; if (lim > 32) lim = 32;
        for (int j = 0; j < lim; j++) {
            int   s = __shfl_sync(FULLM, s2r, j);
            float p = __shfl_sync(FULLM, u1, j), q = __shfl_sync(FULLM, u2, j);
            float2 v = *reinterpret_cast<const float2*>(x + s * D + 2 * l);
            a1x += p * v.x; a1y += p * v.y; a2x += q * v.x; a2y += q * v.y;
        }
    }
    *reinterpret_cast<float2*>(g_agg + w * 128 + 2 * l)      = make_float2(a1x, a1y);
    *reinterpret_cast<float2*>(g_agg + w * 128 + 64 + 2 * l) = make_float2(a2x, a2y);
}

// ---------------- K6: h = LN1(gelu(agg @ [Wp;Wn]^T) + x)  (tf32 MMA) --------
#define S6 72                                 // stride%32==8 -> conflict-free LDS
__global__ void __launch_bounds__(256) k6_gemm_ln1(
        const float* __restrict__ x,
        const float* __restrict__ Wp, const float* __restrict__ Wn,
        const float* __restrict__ g1, const float* __restrict__ b1) {
    __shared__ float sB[128 * S6];
    int tid = threadIdx.x;
    for (int i = tid; i < 8192; i += 256) {
        int n = i >> 7, k = i & 127;
        sB[k * S6 + n] = (k < 64) ? Wp[n * 64 + k] : Wn[n * 64 + (k - 64)];
    }
    __syncthreads();
    int wid = tid >> 5, lane = tid & 31;
    int gid = lane >> 2, tig = lane & 3;
    int strip = blockIdx.x * 8 + wid;
    if (strip >= NSTRIPS) return;
    int r0 = strip * 16 + gid, r1 = r0 + 8;

    float c[8][4];
    #pragma unroll
    for (int nt = 0; nt < 8; nt++)
        c[nt][0] = c[nt][1] = c[nt][2] = c[nt][3] = 0.f;

    #pragma unroll 2
    for (int kk = 0; kk < 16; kk++) {
        int kb = kk * 8;
        float a00 = g_agg[r0 * 128 + kb + tig];
        float a10 = g_agg[r1 * 128 + kb + tig];
        float a01 = g_agg[r0 * 128 + kb + tig + 4];
        float a11 = g_agg[r1 * 128 + kb + tig + 4];
        unsigned ah0 = f2tf(a00), ah1 = f2tf(a10), ah2 = f2tf(a01), ah3 = f2tf(a11);
        unsigned al0 = f2tf(a00 - __uint_as_float(ah0));
        unsigned al1 = f2tf(a10 - __uint_as_float(ah1));
        unsigned al2 = f2tf(a01 - __uint_as_float(ah2));
        unsigned al3 = f2tf(a11 - __uint_as_float(ah3));
        const float* br0 = &sB[(kb + tig) * S6];
        const float* br1 = &sB[(kb + tig + 4) * S6];
        #pragma unroll
        for (int nt = 0; nt < 8; nt++) {
            float b0w = br0[nt * 8 + gid];
            float b1w = br1[nt * 8 + gid];
            mma3(c[nt], ah0, ah1, ah2, ah3, al0, al1, al2, al3, b0w, b1w);
        }
    }
    float s0 = 0.f, q0 = 0.f, s1 = 0.f, q1 = 0.f;
    #pragma unroll
    for (int nt = 0; nt < 8; nt++) {
        int col = nt * 8 + 2 * tig;
        float2 xv0 = *reinterpret_cast<const float2*>(x + r0 * D + col);
        float2 xv1 = *reinterpret_cast<const float2*>(x + r1 * D + col);
        c[nt][0] = gelu_exact(c[nt][0]) + xv0.x;
        c[nt][1] = gelu_exact(c[nt][1]) + xv0.y;
        c[nt][2] = gelu_exact(c[nt][2]) + xv1.x;
        c[nt][3] = gelu_exact(c[nt][3]) + xv1.y;
        s0 += c[nt][0] + c[nt][1]; q0 += c[nt][0] * c[nt][0] + c[nt][1] * c[nt][1];
        s1 += c[nt][2] + c[nt][3]; q1 += c[nt][2] * c[nt][2] + c[nt][3] * c[nt][3];
    }
    #pragma unroll
    for (int o = 1; o <= 2; o <<= 1) {
        s0 += __shfl_xor_sync(FULLM, s0, o);
        q0 += __shfl_xor_sync(FULLM, q0, o);
        s1 += __shfl_xor_sync(FULLM, s1, o);
        q1 += __shfl_xor_sync(FULLM, q1, o);
    }
    float mu0 = s0 * (1.0f / 64.0f), var0 = q0 * (1.0f / 64.0f) - mu0 * mu0;
    float mu1 = s1 * (1.0f / 64.0f), var1 = q1 * (1.0f / 64.0f) - mu1 * mu1;
    float rs0 = rsqrtf(var0 + 1e-5f), rs1 = rsqrtf(var1 + 1e-5f);
    #pragma unroll
    for (int nt = 0; nt < 8; nt++) {
        int col = nt * 8 + 2 * tig;
        float2 gg = *reinterpret_cast<const float2*>(g1 + col);
        float2 bb = *reinterpret_cast<const float2*>(b1 + col);
        float2 o0 = make_float2((c[nt][0] - mu0) * rs0 * gg.x + bb.x,
                                (c[nt][1] - mu0) * rs0 * gg.y + bb.y);
        float2 o1 = make_float2((c[nt][2] - mu1) * rs1 * gg.x + bb.x,
                                (c[nt][3] - mu1) * rs1 * gg.y + bb.y);
        *reinterpret_cast<float2*>(g_h + r0 * D + col) = o0;
        *reinterpret_cast<float2*>(g_h + r1 * D + col) = o1;
    }
}

// ---------------- K7a: t = gelu(h @ W1^T + b1)   (tf32 MMA) -----------------
#define S7 136                                // stride%32==8 -> conflict-free LDS
__global__ void __launch_bounds__(256) k7a_mlp1(
        const float* __restrict__ W1, const float* __restrict__ B1) {
    __shared__ float sB[64 * S7];
    int tid = threadIdx.x;
    for (int i = tid; i < 8192; i += 256) {
        int j = i >> 6, k = i & 63;
        sB[k * S7 + j] = W1[i];
    }
    __syncthreads();
    int wid = tid >> 5, lane = tid & 31;
    int gid = lane >> 2, tig = lane & 3;
    int strip = blockIdx.x * 8 + wid;
    if (strip >= NSTRIPS) return;
    int r0 = strip * 16 + gid, r1 = r0 + 8;

    float c[16][4];
    #pragma unroll
    for (int nt = 0; nt < 16; nt++)
        c[nt][0] = c[nt][1] = c[nt][2] = c[nt][3] = 0.f;

    #pragma unroll 2
    for (int kk = 0; kk < 8; kk++) {
        int kb = kk * 8;
        float a00 = g_h[r0 * D + kb + tig];
        float a10 = g_h[r1 * D + kb + tig];
        float a01 = g_h[r0 * D + kb + tig + 4];
        float a11 = g_h[r1 * D + kb + tig + 4];
        unsigned ah0 = f2tf(a00), ah1 = f2tf(a10), ah2 = f2tf(a01), ah3 = f2tf(a11);
        unsigned al0 = f2tf(a00 - __uint_as_float(ah0));
        unsigned al1 = f2tf(a10 - __uint_as_float(ah1));
        unsigned al2 = f2tf(a01 - __uint_as_float(ah2));
        unsigned al3 = f2tf(a11 - __uint_as_float(ah3));
        const float* br0 = &sB[(kb + tig) * S7];
        const float* br1 = &sB[(kb + tig + 4) * S7];
        #pragma unroll
        for (int nt = 0; nt < 16; nt++) {
            float b0w = br0[nt * 8 + gid];
            float b1w = br1[nt * 8 + gid];
            mma3(c[nt], ah0, ah1, ah2, ah3, al0, al1, al2, al3, b0w, b1w);
        }
    }
    #pragma unroll
    for (int nt = 0; nt < 16; nt++) {
        int col = nt * 8 + 2 * tig;
        float2 bb = *reinterpret_cast<const float2*>(B1 + col);
        float2 t0 = make_float2(gelu_exact(c[nt][0] + bb.x), gelu_exact(c[nt][1] + bb.y));
        float2 t1 = make_float2(gelu_exact(c[nt][2] + bb.x), gelu_exact(c[nt][3] + bb.y));
        *reinterpret_cast<float2*>(g_t + r0 * 128 + col) = t0;
        *reinterpret_cast<float2*>(g_t + r1 * 128 + col) = t1;
    }
}

// ---------------- K7b: out = LN2(t @ W2^T + b2 + h)   (tf32 MMA) ------------
__global__ void __launch_bounds__(256) k7b_mlp2(
        float* __restrict__ out,
        const float* __restrict__ W2, const float* __restrict__ B2,
        const float* __restrict__ g2, const float* __restrict__ b2ln) {
    __shared__ float sB[128 * S6];
    int tid = threadIdx.x;
    for (int i = tid; i < 8192; i += 256) {
        int n = i >> 7, k = i & 127;
        sB[k * S6 + n] = W2[n * 128 + k];
    }
    __syncthreads();
    int wid = tid >> 5, lane = tid & 31;
    int gid = lane >> 2, tig = lane & 3;
    int strip = blockIdx.x * 8 + wid;
    if (strip >= NSTRIPS) return;
    int r0 = strip * 16 + gid, r1 = r0 + 8;

    float c[8][4];
    #pragma unroll
    for (int nt = 0; nt < 8; nt++)
        c[nt][0] = c[nt][1] = c[nt][2] = c[nt][3] = 0.f;

    #pragma unroll 2
    for (int kk = 0; kk < 16; kk++) {
        int kb = kk * 8;
        float a00 = g_t[r0 * 128 + kb + tig];
        float a10 = g_t[r1 * 128 + kb + tig];
        float a01 = g_t[r0 * 128 + kb + tig + 4];
        float a11 = g_t[r1 * 128 + kb + tig + 4];
        unsigned ah0 = f2tf(a00), ah1 = f2tf(a10), ah2 = f2tf(a01), ah3 = f2tf(a11);
        unsigned al0 = f2tf(a00 - __uint_as_float(ah0));
        unsigned al1 = f2tf(a10 - __uint_as_float(ah1));
        unsigned al2 = f2tf(a01 - __uint_as_float(ah2));
        unsigned al3 = f2tf(a11 - __uint_as_float(ah3));
        const float* br0 = &sB[(kb + tig) * S6];
        const float* br1 = &sB[(kb + tig + 4) * S6];
        #pragma unroll
        for (int nt = 0; nt < 8; nt++) {
            float b0w = br0[nt * 8 + gid];
            float b1w = br1[nt * 8 + gid];
            mma3(c[nt], ah0, ah1, ah2, ah3, al0, al1, al2, al3, b0w, b1w);
        }
    }
    float s0 = 0.f, q0 = 0.f, s1 = 0.f, q1 = 0.f;
    #pragma unroll
    for (int nt = 0; nt < 8; nt++) {
        int col = nt * 8 + 2 * tig;
        float2 bb = *reinterpret_cast<const float2*>(B2 + col);
        float2 h0 = *reinterpret_cast<const float2*>(g_h + r0 * D + col);
        float2 h1 = *reinterpret_cast<const float2*>(g_h + r1 * D + col);
        c[nt][0] += bb.x + h0.x;
        c[nt][1] += bb.y + h0.y;
        c[nt][2] += bb.x + h1.x;
        c[nt][3] += bb.y + h1.y;
        s0 += c[nt][0] + c[nt][1]; q0 += c[nt][0] * c[nt][0] + c[nt][1] * c[nt][1];
        s1 += c[nt][2] + c[nt][3]; q1 += c[nt][2] * c[nt][2] + c[nt][3] * c[nt][3];
    }
    #pragma unroll
    for (int o = 1; o <= 2; o <<= 1) {
        s0 += __shfl_xor_sync(FULLM, s0, o);
        q0 += __shfl_xor_sync(FULLM, q0, o);
        s1 += __shfl_xor_sync(FULLM, s1, o);
        q1 += __shfl_xor_sync(FULLM, q1, o);
    }
    float mu0 = s0 * (1.0f / 64.0f), var0 = q0 * (1.0f / 64.0f) - mu0 * mu0;
    float mu1 = s1 * (1.0f / 64.0f), var1 = q1 * (1.0f / 64.0f) - mu1 * mu1;
    float rs0 = rsqrtf(var0 + 1e-5f), rs1 = rsqrtf(var1 + 1e-5f);
    #pragma unroll
    for (int nt = 0; nt < 8; nt++) {
        int col = nt * 8 + 2 * tig;
        float2 gg = *reinterpret_cast<const float2*>(g2 + col);
        float2 bb = *reinterpret_cast<const float2*>(b2ln + col);
        float2 o0 = make_float2((c[nt][0] - mu0) * rs0 * gg.x + bb.x,
                                (c[nt][1] - mu0) * rs0 * gg.y + bb.y);
        float2 o1 = make_float2((c[nt][2] - mu1) * rs1 * gg.x + bb.x,
                                (c[nt][3] - mu1) * rs1 * gg.y + bb.y);
        *reinterpret_cast<float2*>(out + r0 * D + col) = o0;
        *reinterpret_cast<float2*>(out + r1 * D + col) = o1;
    }
}

// ---------------- launcher --------------------------------------------------
extern "C" void kernel_launch(void* const* d_in, const int* in_sizes, int n_in,
                              void* d_out, int out_size) {
    (void)in_sizes; (void)n_in; (void)out_size;
    const float* x    = (const float*)d_in[0];
    const int*   ei   = (const int*)  d_in[1];
    const float* rf   = (const float*)d_in[2];
    const float* Wp   = (const float*)d_in[3];
    const float* Wn   = (const float*)d_in[4];
    const float* attw = (const float*)d_in[5];
    const float* cf   = (const float*)d_in[6];
    const float* W1   = (const float*)d_in[7];
    const float* B1   = (const float*)d_in[8];
    const float* W2   = (const float*)d_in[9];
    const float* B2   = (const float*)d_in[10];
    const float* g1   = (const float*)d_in[11];
    const float* b1   = (const float*)d_in[12];
    const float* g2   = (const float*)d_in[13];
    const float* b2   = (const float*)d_in[14];
    float* out = (float*)d_out;

    const int GBLK = (NSTRIPS + 7) / 8;      // 782

    k1_nodeprep<<<N_NODES / 8, 256>>>(x, attw);
    k2_hist<<<N_EDGES / 256, 256>>>(ei);
    k3_scan<<<1, 1024>>>();
    k4_scatter<<<N_EDGES / 256, 256>>>(ei, rf);
    k5_agg<<<N_NODES / 8, 256>>>(x, cf);
    k6_gemm_ln1<<<GBLK, 256>>>(x, Wp, Wn, g1, b1);
    k7a_mlp1<<<GBLK, 256>>>(W1, B1);
    k7b_mlp2<<<GBLK, 256>>>(out, W2, B2, g2, b2);
}

// round 8
// speedup vs baseline: 1.5214x; 1.3005x over previous
#include <cuda_runtime.h>
#include <math.h>

#define N_NODES 100000
#define N_EDGES 1600000
#define D 64
#define NSTRIPS 6250            // 100000 / 16
#define FULLM 0xffffffffu

// ---------------- scratch (static device globals; no allocations) ----------
__device__ float  g_a1[N_NODES];
__device__ float  g_a2[N_NODES];
__device__ int    g_cnt[N_NODES];
__device__ int    g_off[N_NODES];
__device__ int    g_cur[N_NODES];
__device__ float4 g_csr[N_EDGES];            // (src_as_int, rf, score, pad)
__device__ float  g_agg[N_NODES * 128];      // cols 0..63: s1-weighted, 64..127: s2-weighted
__device__ float  g_h[N_NODES * D];
__device__ float  g_t[N_NODES * 2 * D];

__device__ __forceinline__ float gelu_exact(float v) {
    return 0.5f * v * (1.0f + erff(v * 0.70710678118654752440f));
}

__device__ __forceinline__ unsigned f2tf(float f) {
    unsigned u;
    asm("cvt.rna.tf32.f32 %0, %1;" : "=r"(u) : "f"(f));
    return u;
}

__device__ __forceinline__ void mma_tf32(float c[4],
                                         unsigned a0, unsigned a1, unsigned a2, unsigned a3,
                                         unsigned b0, unsigned b1) {
    asm("mma.sync.aligned.m16n8k8.row.col.f32.tf32.tf32.f32 "
        "{%0,%1,%2,%3},{%4,%5,%6,%7},{%8,%9},{%0,%1,%2,%3};"
        : "+f"(c[0]), "+f"(c[1]), "+f"(c[2]), "+f"(c[3])
        : "r"(a0), "r"(a1), "r"(a2), "r"(a3), "r"(b0), "r"(b1));
}

// 3-term split-tf32 accumulate: c += A*B with ~fp32 accuracy
__device__ __forceinline__ void mma3(float c[4],
                                     unsigned ah0, unsigned ah1, unsigned ah2, unsigned ah3,
                                     unsigned al0, unsigned al1, unsigned al2, unsigned al3,
                                     float b0w, float b1w) {
    unsigned bh0 = f2tf(b0w), bh1 = f2tf(b1w);
    unsigned bl0 = f2tf(b0w - __uint_as_float(bh0));
    unsigned bl1 = f2tf(b1w - __uint_as_float(bh1));
    mma_tf32(c, ah0, ah1, ah2, ah3, bh0, bh1);
    mma_tf32(c, ah0, ah1, ah2, ah3, bl0, bl1);
    mma_tf32(c, al0, al1, al2, al3, bh0, bh1);
}

// ---------------- K1: per-node attention dots + zero counters ---------------
__global__ void k1_nodeprep(const float* __restrict__ x, const float* __restrict__ attw) {
    int w = (blockIdx.x * blockDim.x + threadIdx.x) >> 5;
    int l = threadIdx.x & 31;
    if (w >= N_NODES) return;
    const float* xr = x + w * D;
    float v0 = xr[l], v1 = xr[l + 32];
    float s1 = v0 * attw[l]     + v1 * attw[l + 32];
    float s2 = v0 * attw[D + l] + v1 * attw[D + l + 32];
    #pragma unroll
    for (int o = 16; o; o >>= 1) {
        s1 += __shfl_xor_sync(FULLM, s1, o);
        s2 += __shfl_xor_sync(FULLM, s2, o);
    }
    if (l == 0) { g_a1[w] = s1; g_a2[w] = s2; g_cnt[w] = 0; }
}

// ---------------- K2: histogram of destination degrees ----------------------
__global__ void k2_hist(const int* __restrict__ ei) {
    int e = blockIdx.x * blockDim.x + threadIdx.x;
    if (e >= N_EDGES) return;
    atomicAdd(&g_cnt[ei[N_EDGES + e]], 1);
}

// ---------------- K3: tiled coalesced single-block scan ---------------------
__global__ void k3_scan() {
    __shared__ int wsum[32];
    int t = threadIdx.x, lane = t & 31, wid = t >> 5;
    int base = 0;
    for (int tile = 0; tile < N_NODES; tile += 1024) {
        int idx = tile + t;
        int v = (idx < N_NODES) ? g_cnt[idx] : 0;
        int inc = v;
        #pragma unroll
        for (int o = 1; o < 32; o <<= 1) {
            int u = __shfl_up_sync(FULLM, inc, o);
            if (lane >= o) inc += u;
        }
        if (lane == 31) wsum[wid] = inc;
        __syncthreads();
        if (wid == 0) {
            int ws = wsum[lane];
            int winc = ws;
            #pragma unroll
            for (int o = 1; o < 32; o <<= 1) {
                int u = __shfl_up_sync(FULLM, winc, o);
                if (lane >= o) winc += u;
            }
            wsum[lane] = winc;
        }
        __syncthreads();
        int excl = base + inc - v + (wid ? wsum[wid - 1] : 0);
        if (idx < N_NODES) { g_off[idx] = excl; g_cur[idx] = excl; }
        base += wsum[31];
        __syncthreads();
    }
}

// ---------------- K4: scatter edges into CSR (packed float4) ----------------
__global__ void k4_scatter(const int* __restrict__ ei, const float* __restrict__ rf) {
    int e = blockIdx.x * blockDim.x + threadIdx.x;
    if (e >= N_EDGES) return;
    int s = ei[e], d = ei[N_EDGES + e];
    int pos = atomicAdd(&g_cur[d], 1);
    g_csr[pos] = make_float4(__int_as_float(s), rf[e], g_a1[s] + g_a2[d], 0.0f);
}

// ---------------- K5: warp-per-node softmax + half-warp float4 gather -------
__global__ void k5_agg(const float* __restrict__ x, const float* __restrict__ cf) {
    int w = (blockIdx.x * blockDim.x + threadIdx.x) >> 5;
    int l = threadIdx.x & 31;
    if (w >= N_NODES) return;
    int beg = g_off[w], cnt = g_cnt[w];
    float alpha = 1.0f / (1.0f + __expf(-cf[0]));

    // stage first 32 edges lane-parallel (coalesced 512B)
    float4 ed = make_float4(0.f, 0.f, -1e30f, 0.f);   // src=0, weight will be 0
    if (l < cnt) ed = g_csr[beg + l];

    // segment max
    float m = ed.z;
    for (int i = 32 + l; i < cnt; i += 32) m = fmaxf(m, g_csr[beg + i].z);
    #pragma unroll
    for (int o = 16; o; o >>= 1) m = fmaxf(m, __shfl_xor_sync(FULLM, m, o));

    // segment denom
    float e0 = (l < cnt) ? __expf(ed.z - m) : 0.f;
    float den = e0;
    for (int i = 32 + l; i < cnt; i += 32) den += __expf(g_csr[beg + i].z - m);
    #pragma unroll
    for (int o = 16; o; o >>= 1) den += __shfl_xor_sync(FULLM, den, o);
    float inv = (cnt > 0) ? (1.0f / den) : 0.f;

    // per-lane weights for staged edges (0 for lanes >= cnt; src=0 there)
    float w1 = e0 * inv * alpha * ed.y;
    float w2 = e0 * inv * (1.0f - alpha);
    int   sr = __float_as_int(ed.x);

    int h = l >> 4, j = l & 15;          // half-warp id, lane-in-half
    float4 a1 = make_float4(0.f, 0.f, 0.f, 0.f);
    float4 a2 = make_float4(0.f, 0.f, 0.f, 0.f);

    int n0  = cnt < 32 ? cnt : 32;
    int n0e = (n0 + 1) & ~1;             // round up to even (extra edge has weight 0)
    int i = 0;
    // 4 batches x 2 edges per iteration: 8 independent LDG.128 streams
    for (; i + 8 <= n0e; i += 8) {
        #pragma unroll
        for (int b = 0; b < 4; b++) {
            int   e  = i + 2 * b + h;
            int   se = __shfl_sync(FULLM, sr, e);
            float p  = __shfl_sync(FULLM, w1, e);
            float q  = __shfl_sync(FULLM, w2, e);
            float4 v = *reinterpret_cast<const float4*>(x + se * D + 4 * j);
            a1.x += p * v.x; a1.y += p * v.y; a1.z += p * v.z; a1.w += p * v.w;
            a2.x += q * v.x; a2.y += q * v.y; a2.z += q * v.z; a2.w += q * v.w;
        }
    }
    for (; i < n0e; i += 2) {
        int   e  = i + h;
        int   se = __shfl_sync(FULLM, sr, e);
        float p  = __shfl_sync(FULLM, w1, e);
        float q  = __shfl_sync(FULLM, w2, e);
        float4 v = *reinterpret_cast<const float4*>(x + se * D + 4 * j);
        a1.x += p * v.x; a1.y += p * v.y; a1.z += p * v.z; a1.w += p * v.w;
        a2.x += q * v.x; a2.y += q * v.y; a2.z += q * v.z; a2.w += q * v.w;
    }
    // rare overflow chunks (degree > 32)
    for (int base2 = 32; base2 < cnt; base2 += 32) {
        int k = base2 + l;
        float4 e2 = make_float4(0.f, 0.f, 0.f, 0.f);     // src=0
        float ew = 0.f;
        if (k < cnt) { e2 = g_csr[beg + k]; ew = __expf(e2.z - m) * inv; }
        float u1 = ew * alpha * e2.y;
        float u2 = ew * (1.0f - alpha);
        int  s2r = __float_as_int(e2.x);
        int lim = cnt - base2; if (lim > 32) lim = 32;
        int lime = (lim + 1) & ~1;
        for (int ii = 0; ii < lime; ii += 2) {
            int   e  = ii + h;
            int   se = __shfl_sync(FULLM, s2r, e);
            float p  = __shfl_sync(FULLM, u1, e);
            float q  = __shfl_sync(FULLM, u2, e);
            float4 v = *reinterpret_cast<const float4*>(x + se * D + 4 * j);
            a1.x += p * v.x; a1.y += p * v.y; a1.z += p * v.z; a1.w += p * v.w;
            a2.x += q * v.x; a2.y += q * v.y; a2.z += q * v.z; a2.w += q * v.w;
        }
    }
    // combine half-warps
    a1.x += __shfl_xor_sync(FULLM, a1.x, 16);
    a1.y += __shfl_xor_sync(FULLM, a1.y, 16);
    a1.z += __shfl_xor_sync(FULLM, a1.z, 16);
    a1.w += __shfl_xor_sync(FULLM, a1.w, 16);
    a2.x += __shfl_xor_sync(FULLM, a2.x, 16);
    a2.y += __shfl_xor_sync(FULLM, a2.y, 16);
    a2.z += __shfl_xor_sync(FULLM, a2.z, 16);
    a2.w += __shfl_xor_sync(FULLM, a2.w, 16);
    // lanes 0-15 write agg1 (dims 4j), lanes 16-31 write agg2 (dims 64+4j)
    float4 sel = h ? a2 : a1;
    *reinterpret_cast<float4*>(g_agg + w * 128 + 4 * l) = sel;
}

// ---------------- K6: h = LN1(gelu(agg @ [Wp;Wn]^T) + x)  (tf32 MMA) --------
#define S6 72                                 // stride%32==8 -> conflict-free LDS
__global__ void __launch_bounds__(256) k6_gemm_ln1(
        const float* __restrict__ x,
        const float* __restrict__ Wp, const float* __restrict__ Wn,
        const float* __restrict__ g1, const float* __restrict__ b1) {
    __shared__ float sB[128 * S6];
    int tid = threadIdx.x;
    for (int i = tid; i < 8192; i += 256) {
        int n = i >> 7, k = i & 127;
        sB[k * S6 + n] = (k < 64) ? Wp[n * 64 + k] : Wn[n * 64 + (k - 64)];
    }
    __syncthreads();
    int wid = tid >> 5, lane = tid & 31;
    int gid = lane >> 2, tig = lane & 3;
    int strip = blockIdx.x * 8 + wid;
    if (strip >= NSTRIPS) return;
    int r0 = strip * 16 + gid, r1 = r0 + 8;

    float c[8][4];
    #pragma unroll
    for (int nt = 0; nt < 8; nt++)
        c[nt][0] = c[nt][1] = c[nt][2] = c[nt][3] = 0.f;

    #pragma unroll 2
    for (int kk = 0; kk < 16; kk++) {
        int kb = kk * 8;
        float a00 = g_agg[r0 * 128 + kb + tig];
        float a10 = g_agg[r1 * 128 + kb + tig];
        float a01 = g_agg[r0 * 128 + kb + tig + 4];
        float a11 = g_agg[r1 * 128 + kb + tig + 4];
        unsigned ah0 = f2tf(a00), ah1 = f2tf(a10), ah2 = f2tf(a01), ah3 = f2tf(a11);
        unsigned al0 = f2tf(a00 - __uint_as_float(ah0));
        unsigned al1 = f2tf(a10 - __uint_as_float(ah1));
        unsigned al2 = f2tf(a01 - __uint_as_float(ah2));
        unsigned al3 = f2tf(a11 - __uint_as_float(ah3));
        const float* br0 = &sB[(kb + tig) * S6];
        const float* br1 = &sB[(kb + tig + 4) * S6];
        #pragma unroll
        for (int nt = 0; nt < 8; nt++) {
            float b0w = br0[nt * 8 + gid];
            float b1w = br1[nt * 8 + gid];
            mma3(c[nt], ah0, ah1, ah2, ah3, al0, al1, al2, al3, b0w, b1w);
        }
    }
    float s0 = 0.f, q0 = 0.f, s1 = 0.f, q1 = 0.f;
    #pragma unroll
    for (int nt = 0; nt < 8; nt++) {
        int col = nt * 8 + 2 * tig;
        float2 xv0 = *reinterpret_cast<const float2*>(x + r0 * D + col);
        float2 xv1 = *reinterpret_cast<const float2*>(x + r1 * D + col);
        c[nt][0] = gelu_exact(c[nt][0]) + xv0.x;
        c[nt][1] = gelu_exact(c[nt][1]) + xv0.y;
        c[nt][2] = gelu_exact(c[nt][2]) + xv1.x;
        c[nt][3] = gelu_exact(c[nt][3]) + xv1.y;
        s0 += c[nt][0] + c[nt][1]; q0 += c[nt][0] * c[nt][0] + c[nt][1] * c[nt][1];
        s1 += c[nt][2] + c[nt][3]; q1 += c[nt][2] * c[nt][2] + c[nt][3] * c[nt][3];
    }
    #pragma unroll
    for (int o = 1; o <= 2; o <<= 1) {
        s0 += __shfl_xor_sync(FULLM, s0, o);
        q0 += __shfl_xor_sync(FULLM, q0, o);
        s1 += __shfl_xor_sync(FULLM, s1, o);
        q1 += __shfl_xor_sync(FULLM, q1, o);
    }
    float mu0 = s0 * (1.0f / 64.0f), var0 = q0 * (1.0f / 64.0f) - mu0 * mu0;
    float mu1 = s1 * (1.0f / 64.0f), var1 = q1 * (1.0f / 64.0f) - mu1 * mu1;
    float rs0 = rsqrtf(var0 + 1e-5f), rs1 = rsqrtf(var1 + 1e-5f);
    #pragma unroll
    for (int nt = 0; nt < 8; nt++) {
        int col = nt * 8 + 2 * tig;
        float2 gg = *reinterpret_cast<const float2*>(g1 + col);
        float2 bb = *reinterpret_cast<const float2*>(b1 + col);
        float2 o0 = make_float2((c[nt][0] - mu0) * rs0 * gg.x + bb.x,
                                (c[nt][1] - mu0) * rs0 * gg.y + bb.y);
        float2 o1 = make_float2((c[nt][2] - mu1) * rs1 * gg.x + bb.x,
                                (c[nt][3] - mu1) * rs1 * gg.y + bb.y);
        *reinterpret_cast<float2*>(g_h + r0 * D + col) = o0;
        *reinterpret_cast<float2*>(g_h + r1 * D + col) = o1;
    }
}

// ---------------- K7a: t = gelu(h @ W1^T + b1)   (tf32 MMA) -----------------
#define S7 136                                // stride%32==8 -> conflict-free LDS
__global__ void __launch_bounds__(256) k7a_mlp1(
        const float* __restrict__ W1, const float* __restrict__ B1) {
    __shared__ float sB[64 * S7];
    int tid = threadIdx.x;
    for (int i = tid; i < 8192; i += 256) {
        int j = i >> 6, k = i & 63;
        sB[k * S7 + j] = W1[i];
    }
    __syncthreads();
    int wid = tid >> 5, lane = tid & 31;
    int gid = lane >> 2, tig = lane & 3;
    int strip = blockIdx.x * 8 + wid;
    if (strip >= NSTRIPS) return;
    int r0 = strip * 16 + gid, r1 = r0 + 8;

    float c[16][4];
    #pragma unroll
    for (int nt = 0; nt < 16; nt++)
        c[nt][0] = c[nt][1] = c[nt][2] = c[nt][3] = 0.f;

    #pragma unroll 2
    for (int kk = 0; kk < 8; kk++) {
        int kb = kk * 8;
        float a00 = g_h[r0 * D + kb + tig];
        float a10 = g_h[r1 * D + kb + tig];
        float a01 = g_h[r0 * D + kb + tig + 4];
        float a11 = g_h[r1 * D + kb + tig + 4];
        unsigned ah0 = f2tf(a00), ah1 = f2tf(a10), ah2 = f2tf(a01), ah3 = f2tf(a11);
        unsigned al0 = f2tf(a00 - __uint_as_float(ah0));
        unsigned al1 = f2tf(a10 - __uint_as_float(ah1));
        unsigned al2 = f2tf(a01 - __uint_as_float(ah2));
        unsigned al3 = f2tf(a11 - __uint_as_float(ah3));
        const float* br0 = &sB[(kb + tig) * S7];
        const float* br1 = &sB[(kb + tig + 4) * S7];
        #pragma unroll
        for (int nt = 0; nt < 16; nt++) {
            float b0w = br0[nt * 8 + gid];
            float b1w = br1[nt * 8 + gid];
            mma3(c[nt], ah0, ah1, ah2, ah3, al0, al1, al2, al3, b0w, b1w);
        }
    }
    #pragma unroll
    for (int nt = 0; nt < 16; nt++) {
        int col = nt * 8 + 2 * tig;
        float2 bb = *reinterpret_cast<const float2*>(B1 + col);
        float2 t0 = make_float2(gelu_exact(c[nt][0] + bb.x), gelu_exact(c[nt][1] + bb.y));
        float2 t1 = make_float2(gelu_exact(c[nt][2] + bb.x), gelu_exact(c[nt][3] + bb.y));
        *reinterpret_cast<float2*>(g_t + r0 * 128 + col) = t0;
        *reinterpret_cast<float2*>(g_t + r1 * 128 + col) = t1;
    }
}

// ---------------- K7b: out = LN2(t @ W2^T + b2 + h)   (tf32 MMA) ------------
__global__ void __launch_bounds__(256) k7b_mlp2(
        float* __restrict__ out,
        const float* __restrict__ W2, const float* __restrict__ B2,
        const float* __restrict__ g2, const float* __restrict__ b2ln) {
    __shared__ float sB[128 * S6];
    int tid = threadIdx.x;
    for (int i = tid; i < 8192; i += 256) {
        int n = i >> 7, k = i & 127;
        sB[k * S6 + n] = W2[n * 128 + k];
    }
    __syncthreads();
    int wid = tid >> 5, lane = tid & 31;
    int gid = lane >> 2, tig = lane & 3;
    int strip = blockIdx.x * 8 + wid;
    if (strip >= NSTRIPS) return;
    int r0 = strip * 16 + gid, r1 = r0 + 8;

    float c[8][4];
    #pragma unroll
    for (int nt = 0; nt < 8; nt++)
        c[nt][0] = c[nt][1] = c[nt][2] = c[nt][3] = 0.f;

    #pragma unroll 2
    for (int kk = 0; kk < 16; kk++) {
        int kb = kk * 8;
        float a00 = g_t[r0 * 128 + kb + tig];
        float a10 = g_t[r1 * 128 + kb + tig];
        float a01 = g_t[r0 * 128 + kb + tig + 4];
        float a11 = g_t[r1 * 128 + kb + tig + 4];
        unsigned ah0 = f2tf(a00), ah1 = f2tf(a10), ah2 = f2tf(a01), ah3 = f2tf(a11);
        unsigned al0 = f2tf(a00 - __uint_as_float(ah0));
        unsigned al1 = f2tf(a10 - __uint_as_float(ah1));
        unsigned al2 = f2tf(a01 - __uint_as_float(ah2));
        unsigned al3 = f2tf(a11 - __uint_as_float(ah3));
        const float* br0 = &sB[(kb + tig) * S6];
        const float* br1 = &sB[(kb + tig + 4) * S6];
        #pragma unroll
        for (int nt = 0; nt < 8; nt++) {
            float b0w = br0[nt * 8 + gid];
            float b1w = br1[nt * 8 + gid];
            mma3(c[nt], ah0, ah1, ah2, ah3, al0, al1, al2, al3, b0w, b1w);
        }
    }
    float s0 = 0.f, q0 = 0.f, s1 = 0.f, q1 = 0.f;
    #pragma unroll
    for (int nt = 0; nt < 8; nt++) {
        int col = nt * 8 + 2 * tig;
        float2 bb = *reinterpret_cast<const float2*>(B2 + col);
        float2 h0 = *reinterpret_cast<const float2*>(g_h + r0 * D + col);
        float2 h1 = *reinterpret_cast<const float2*>(g_h + r1 * D + col);
        c[nt][0] += bb.x + h0.x;
        c[nt][1] += bb.y + h0.y;
        c[nt][2] += bb.x + h1.x;
        c[nt][3] += bb.y + h1.y;
        s0 += c[nt][0] + c[nt][1]; q0 += c[nt][0] * c[nt][0] + c[nt][1] * c[nt][1];
        s1 += c[nt][2] + c[nt][3]; q1 += c[nt][2] * c[nt][2] + c[nt][3] * c[nt][3];
    }
    #pragma unroll
    for (int o = 1; o <= 2; o <<= 1) {
        s0 += __shfl_xor_sync(FULLM, s0, o);
        q0 += __shfl_xor_sync(FULLM, q0, o);
        s1 += __shfl_xor_sync(FULLM, s1, o);
        q1 += __shfl_xor_sync(FULLM, q1, o);
    }
    float mu0 = s0 * (1.0f / 64.0f), var0 = q0 * (1.0f / 64.0f) - mu0 * mu0;
    float mu1 = s1 * (1.0f / 64.0f), var1 = q1 * (1.0f / 64.0f) - mu1 * mu1;
    float rs0 = rsqrtf(var0 + 1e-5f), rs1 = rsqrtf(var1 + 1e-5f);
    #pragma unroll
    for (int nt = 0; nt < 8; nt++) {
        int col = nt * 8 + 2 * tig;
        float2 gg = *reinterpret_cast<const float2*>(g2 + col);
        float2 bb = *reinterpret_cast<const float2*>(b2ln + col);
        float2 o0 = make_float2((c[nt][0] - mu0) * rs0 * gg.x + bb.x,
                                (c[nt][1] - mu0) * rs0 * gg.y + bb.y);
        float2 o1 = make_float2((c[nt][2] - mu1) * rs1 * gg.x + bb.x,
                                (c[nt][3] - mu1) * rs1 * gg.y + bb.y);
        *reinterpret_cast<float2*>(out + r0 * D + col) = o0;
        *reinterpret_cast<float2*>(out + r1 * D + col) = o1;
    }
}

// ---------------- launcher --------------------------------------------------
extern "C" void kernel_launch(void* const* d_in, const int* in_sizes, int n_in,
                              void* d_out, int out_size) {
    (void)in_sizes; (void)n_in; (void)out_size;
    const float* x    = (const float*)d_in[0];
    const int*   ei   = (const int*)  d_in[1];
    const float* rf   = (const float*)d_in[2];
    const float* Wp   = (const float*)d_in[3];
    const float* Wn   = (const float*)d_in[4];
    const float* attw = (const float*)d_in[5];
    const float* cf   = (const float*)d_in[6];
    const float* W1   = (const float*)d_in[7];
    const float* B1   = (const float*)d_in[8];
    const float* W2   = (const float*)d_in[9];
    const float* B2   = (const float*)d_in[10];
    const float* g1   = (const float*)d_in[11];
    const float* b1   = (const float*)d_in[12];
    const float* g2   = (const float*)d_in[13];
    const float* b2   = (const float*)d_in[14];
    float* out = (float*)d_out;

    const int GBLK = (NSTRIPS + 7) / 8;      // 782

    k1_nodeprep<<<N_NODES / 8, 256>>>(x, attw);
    k2_hist<<<N_EDGES / 256, 256>>>(ei);
    k3_scan<<<1, 1024>>>();
    k4_scatter<<<N_EDGES / 256, 256>>>(ei, rf);
    k5_agg<<<N_NODES / 8, 256>>>(x, cf);
    k6_gemm_ln1<<<GBLK, 256>>>(x, Wp, Wn, g1, b1);
    k7a_mlp1<<<GBLK, 256>>>(W1, B1);
    k7b_mlp2<<<GBLK, 256>>>(out, W2, B2, g2, b2);
}

// round 9
// speedup vs baseline: 1.5741x; 1.0347x over previous
#include <cuda_runtime.h>
#include <math.h>

#define N_NODES 100000
#define N_EDGES 1600000
#define D 64
#define NSTRIPS 6250            // 100000 / 16
#define FULLM 0xffffffffu

// ---------------- scratch (static device globals; no allocations) ----------
__device__ float  g_a1[N_NODES];
__device__ float  g_a2[N_NODES];
__device__ int    g_cnt[N_NODES];       // starts zeroed; re-zeroed by k5 each pass
__device__ int    g_off[N_NODES];
__device__ int    g_cur[N_NODES];
__device__ float4 g_csr[N_EDGES];       // (src_as_int, rf, score, pad)
__device__ float  g_agg[N_NODES * 128]; // cols 0..63: s1-weighted, 64..127: s2-weighted
__device__ float  g_h[N_NODES * D];

__device__ __forceinline__ float gelu_exact(float v) {
    return 0.5f * v * (1.0f + erff(v * 0.70710678118654752440f));
}

__device__ __forceinline__ unsigned f2tf(float f) {
    unsigned u;
    asm("cvt.rna.tf32.f32 %0, %1;" : "=r"(u) : "f"(f));
    return u;
}

__device__ __forceinline__ void mma_tf32(float c[4],
                                         unsigned a0, unsigned a1, unsigned a2, unsigned a3,
                                         unsigned b0, unsigned b1) {
    asm("mma.sync.aligned.m16n8k8.row.col.f32.tf32.tf32.f32 "
        "{%0,%1,%2,%3},{%4,%5,%6,%7},{%8,%9},{%0,%1,%2,%3};"
        : "+f"(c[0]), "+f"(c[1]), "+f"(c[2]), "+f"(c[3])
        : "r"(a0), "r"(a1), "r"(a2), "r"(a3), "r"(b0), "r"(b1));
}

// 3-term split-tf32 accumulate: c += A*B with ~fp32 accuracy
__device__ __forceinline__ void mma3(float c[4],
                                     unsigned ah0, unsigned ah1, unsigned ah2, unsigned ah3,
                                     unsigned al0, unsigned al1, unsigned al2, unsigned al3,
                                     float b0w, float b1w) {
    unsigned bh0 = f2tf(b0w), bh1 = f2tf(b1w);
    unsigned bl0 = f2tf(b0w - __uint_as_float(bh0));
    unsigned bl1 = f2tf(b1w - __uint_as_float(bh1));
    mma_tf32(c, ah0, ah1, ah2, ah3, bh0, bh1);
    mma_tf32(c, ah0, ah1, ah2, ah3, bl0, bl1);
    mma_tf32(c, al0, al1, al2, al3, bh0, bh1);
}

// ---------------- K12: per-node attention dots + edge histogram (merged) ----
__global__ void k12_prep(const float* __restrict__ x, const float* __restrict__ attw,
                         const int* __restrict__ ei) {
    int gt = blockIdx.x * blockDim.x + threadIdx.x;
    // edge-histogram phase (3.2M threads cover 1.6M edges)
    if (gt < N_EDGES) atomicAdd(&g_cnt[ei[N_EDGES + gt]], 1);
    // node-dot phase (warp per node)
    int w = gt >> 5;
    int l = gt & 31;
    if (w >= N_NODES) return;
    const float* xr = x + w * D;
    float v0 = xr[l], v1 = xr[l + 32];
    float s1 = v0 * attw[l]     + v1 * attw[l + 32];
    float s2 = v0 * attw[D + l] + v1 * attw[D + l + 32];
    #pragma unroll
    for (int o = 16; o; o >>= 1) {
        s1 += __shfl_xor_sync(FULLM, s1, o);
        s2 += __shfl_xor_sync(FULLM, s2, o);
    }
    if (l == 0) { g_a1[w] = s1; g_a2[w] = s2; }
}

// ---------------- K3: tiled coalesced single-block scan ---------------------
__global__ void k3_scan() {
    __shared__ int wsum[32];
    int t = threadIdx.x, lane = t & 31, wid = t >> 5;
    int base = 0;
    for (int tile = 0; tile < N_NODES; tile += 1024) {
        int idx = tile + t;
        int v = (idx < N_NODES) ? g_cnt[idx] : 0;
        int inc = v;
        #pragma unroll
        for (int o = 1; o < 32; o <<= 1) {
            int u = __shfl_up_sync(FULLM, inc, o);
            if (lane >= o) inc += u;
        }
        if (lane == 31) wsum[wid] = inc;
        __syncthreads();
        if (wid == 0) {
            int ws = wsum[lane];
            int winc = ws;
            #pragma unroll
            for (int o = 1; o < 32; o <<= 1) {
                int u = __shfl_up_sync(FULLM, winc, o);
                if (lane >= o) winc += u;
            }
            wsum[lane] = winc;
        }
        __syncthreads();
        int excl = base + inc - v + (wid ? wsum[wid - 1] : 0);
        if (idx < N_NODES) { g_off[idx] = excl; g_cur[idx] = excl; }
        base += wsum[31];
        __syncthreads();
    }
}

// ---------------- K4: scatter edges into CSR (packed float4) ----------------
__global__ void k4_scatter(const int* __restrict__ ei, const float* __restrict__ rf) {
    int e = blockIdx.x * blockDim.x + threadIdx.x;
    if (e >= N_EDGES) return;
    int s = ei[e], d = ei[N_EDGES + e];
    int pos = atomicAdd(&g_cur[d], 1);
    g_csr[pos] = make_float4(__int_as_float(s), rf[e], g_a1[s] + g_a2[d], 0.0f);
}

// ---------------- K5: warp-per-node softmax + half-warp float4 gather -------
__global__ void k5_agg(const float* __restrict__ x, const float* __restrict__ cf) {
    int w = (blockIdx.x * blockDim.x + threadIdx.x) >> 5;
    int l = threadIdx.x & 31;
    if (w >= N_NODES) return;
    int beg = g_off[w], cnt = g_cnt[w];
    float alpha = 1.0f / (1.0f + __expf(-cf[0]));

    // stage first 32 edges lane-parallel (coalesced 512B)
    float4 ed = make_float4(0.f, 0.f, -1e30f, 0.f);   // src=0, weight will be 0
    if (l < cnt) ed = g_csr[beg + l];

    // segment max
    float m = ed.z;
    for (int i = 32 + l; i < cnt; i += 32) m = fmaxf(m, g_csr[beg + i].z);
    #pragma unroll
    for (int o = 16; o; o >>= 1) m = fmaxf(m, __shfl_xor_sync(FULLM, m, o));

    // segment denom
    float e0 = (l < cnt) ? __expf(ed.z - m) : 0.f;
    float den = e0;
    for (int i = 32 + l; i < cnt; i += 32) den += __expf(g_csr[beg + i].z - m);
    #pragma unroll
    for (int o = 16; o; o >>= 1) den += __shfl_xor_sync(FULLM, den, o);
    float inv = (cnt > 0) ? (1.0f / den) : 0.f;

    // per-lane weights for staged edges (0 for lanes >= cnt; src=0 there)
    float w1 = e0 * inv * alpha * ed.y;
    float w2 = e0 * inv * (1.0f - alpha);
    int   sr = __float_as_int(ed.x);

    int h = l >> 4, j = l & 15;          // half-warp id, lane-in-half
    float4 a1 = make_float4(0.f, 0.f, 0.f, 0.f);
    float4 a2 = make_float4(0.f, 0.f, 0.f, 0.f);

    int n0  = cnt < 32 ? cnt : 32;
    int n0e = (n0 + 1) & ~1;             // round up to even (extra edge has weight 0)
    int i = 0;
    // 4 batches x 2 edges per iteration: 8 independent LDG.128 streams
    for (; i + 8 <= n0e; i += 8) {
        #pragma unroll
        for (int b = 0; b < 4; b++) {
            int   e  = i + 2 * b + h;
            int   se = __shfl_sync(FULLM, sr, e);
            float p  = __shfl_sync(FULLM, w1, e);
            float q  = __shfl_sync(FULLM, w2, e);
            float4 v = *reinterpret_cast<const float4*>(x + se * D + 4 * j);
            a1.x += p * v.x; a1.y += p * v.y; a1.z += p * v.z; a1.w += p * v.w;
            a2.x += q * v.x; a2.y += q * v.y; a2.z += q * v.z; a2.w += q * v.w;
        }
    }
    for (; i < n0e; i += 2) {
        int   e  = i + h;
        int   se = __shfl_sync(FULLM, sr, e);
        float p  = __shfl_sync(FULLM, w1, e);
        float q  = __shfl_sync(FULLM, w2, e);
        float4 v = *reinterpret_cast<const float4*>(x + se * D + 4 * j);
        a1.x += p * v.x; a1.y += p * v.y; a1.z += p * v.z; a1.w += p * v.w;
        a2.x += q * v.x; a2.y += q * v.y; a2.z += q * v.z; a2.w += q * v.w;
    }
    // rare overflow chunks (degree > 32)
    for (int base2 = 32; base2 < cnt; base2 += 32) {
        int k = base2 + l;
        float4 e2 = make_float4(0.f, 0.f, 0.f, 0.f);     // src=0
        float ew = 0.f;
        if (k < cnt) { e2 = g_csr[beg + k]; ew = __expf(e2.z - m) * inv; }
        float u1 = ew * alpha * e2.y;
        float u2 = ew * (1.0f - alpha);
        int  s2r = __float_as_int(e2.x);
        int lim = cnt - base2; if (lim > 32) lim = 32;
        int lime = (lim + 1) & ~1;
        for (int ii = 0; ii < lime; ii += 2) {
            int   e  = ii + h;
            int   se = __shfl_sync(FULLM, s2r, e);
            float p  = __shfl_sync(FULLM, u1, e);
            float q  = __shfl_sync(FULLM, u2, e);
            float4 v = *reinterpret_cast<const float4*>(x + se * D + 4 * j);
            a1.x += p * v.x; a1.y += p * v.y; a1.z += p * v.z; a1.w += p * v.w;
            a2.x += q * v.x; a2.y += q * v.y; a2.z += q * v.z; a2.w += q * v.w;
        }
    }
    // combine half-warps
    a1.x += __shfl_xor_sync(FULLM, a1.x, 16);
    a1.y += __shfl_xor_sync(FULLM, a1.y, 16);
    a1.z += __shfl_xor_sync(FULLM, a1.z, 16);
    a1.w += __shfl_xor_sync(FULLM, a1.w, 16);
    a2.x += __shfl_xor_sync(FULLM, a2.x, 16);
    a2.y += __shfl_xor_sync(FULLM, a2.y, 16);
    a2.z += __shfl_xor_sync(FULLM, a2.z, 16);
    a2.w += __shfl_xor_sync(FULLM, a2.w, 16);
    // lanes 0-15 write agg1 (dims 4j), lanes 16-31 write agg2 (dims 64+4j)
    float4 sel = h ? a2 : a1;
    *reinterpret_cast<float4*>(g_agg + w * 128 + 4 * l) = sel;
    // reset histogram counter for the next graph replay
    if (l == 0) g_cnt[w] = 0;
}

// ---------------- K6: h = LN1(gelu(agg @ [Wp;Wn]^T) + x)  (tf32 MMA) --------
#define S6 72                                 // stride%32==8 -> conflict-free LDS
__global__ void __launch_bounds__(256) k6_gemm_ln1(
        const float* __restrict__ x,
        const float* __restrict__ Wp, const float* __restrict__ Wn,
        const float* __restrict__ g1, const float* __restrict__ b1) {
    __shared__ float sB[128 * S6];
    int tid = threadIdx.x;
    for (int i = tid; i < 8192; i += 256) {
        int n = i >> 7, k = i & 127;
        sB[k * S6 + n] = (k < 64) ? Wp[n * 64 + k] : Wn[n * 64 + (k - 64)];
    }
    __syncthreads();
    int wid = tid >> 5, lane = tid & 31;
    int gid = lane >> 2, tig = lane & 3;
    int strip = blockIdx.x * 8 + wid;
    if (strip >= NSTRIPS) return;
    int r0 = strip * 16 + gid, r1 = r0 + 8;

    float c[8][4];
    #pragma unroll
    for (int nt = 0; nt < 8; nt++)
        c[nt][0] = c[nt][1] = c[nt][2] = c[nt][3] = 0.f;

    #pragma unroll 2
    for (int kk = 0; kk < 16; kk++) {
        int kb = kk * 8;
        float a00 = g_agg[r0 * 128 + kb + tig];
        float a10 = g_agg[r1 * 128 + kb + tig];
        float a01 = g_agg[r0 * 128 + kb + tig + 4];
        float a11 = g_agg[r1 * 128 + kb + tig + 4];
        unsigned ah0 = f2tf(a00), ah1 = f2tf(a10), ah2 = f2tf(a01), ah3 = f2tf(a11);
        unsigned al0 = f2tf(a00 - __uint_as_float(ah0));
        unsigned al1 = f2tf(a10 - __uint_as_float(ah1));
        unsigned al2 = f2tf(a01 - __uint_as_float(ah2));
        unsigned al3 = f2tf(a11 - __uint_as_float(ah3));
        const float* br0 = &sB[(kb + tig) * S6];
        const float* br1 = &sB[(kb + tig + 4) * S6];
        #pragma unroll
        for (int nt = 0; nt < 8; nt++) {
            float b0w = br0[nt * 8 + gid];
            float b1w = br1[nt * 8 + gid];
            mma3(c[nt], ah0, ah1, ah2, ah3, al0, al1, al2, al3, b0w, b1w);
        }
    }
    float s0 = 0.f, q0 = 0.f, s1 = 0.f, q1 = 0.f;
    #pragma unroll
    for (int nt = 0; nt < 8; nt++) {
        int col = nt * 8 + 2 * tig;
        float2 xv0 = *reinterpret_cast<const float2*>(x + r0 * D + col);
        float2 xv1 = *reinterpret_cast<const float2*>(x + r1 * D + col);
        c[nt][0] = gelu_exact(c[nt][0]) + xv0.x;
        c[nt][1] = gelu_exact(c[nt][1]) + xv0.y;
        c[nt][2] = gelu_exact(c[nt][2]) + xv1.x;
        c[nt][3] = gelu_exact(c[nt][3]) + xv1.y;
        s0 += c[nt][0] + c[nt][1]; q0 += c[nt][0] * c[nt][0] + c[nt][1] * c[nt][1];
        s1 += c[nt][2] + c[nt][3]; q1 += c[nt][2] * c[nt][2] + c[nt][3] * c[nt][3];
    }
    #pragma unroll
    for (int o = 1; o <= 2; o <<= 1) {
        s0 += __shfl_xor_sync(FULLM, s0, o);
        q0 += __shfl_xor_sync(FULLM, q0, o);
        s1 += __shfl_xor_sync(FULLM, s1, o);
        q1 += __shfl_xor_sync(FULLM, q1, o);
    }
    float mu0 = s0 * (1.0f / 64.0f), var0 = q0 * (1.0f / 64.0f) - mu0 * mu0;
    float mu1 = s1 * (1.0f / 64.0f), var1 = q1 * (1.0f / 64.0f) - mu1 * mu1;
    float rs0 = rsqrtf(var0 + 1e-5f), rs1 = rsqrtf(var1 + 1e-5f);
    #pragma unroll
    for (int nt = 0; nt < 8; nt++) {
        int col = nt * 8 + 2 * tig;
        float2 gg = *reinterpret_cast<const float2*>(g1 + col);
        float2 bb = *reinterpret_cast<const float2*>(b1 + col);
        float2 o0 = make_float2((c[nt][0] - mu0) * rs0 * gg.x + bb.x,
                                (c[nt][1] - mu0) * rs0 * gg.y + bb.y);
        float2 o1 = make_float2((c[nt][2] - mu1) * rs1 * gg.x + bb.x,
                                (c[nt][3] - mu1) * rs1 * gg.y + bb.y);
        *reinterpret_cast<float2*>(g_h + r0 * D + col) = o0;
        *reinterpret_cast<float2*>(g_h + r1 * D + col) = o1;
    }
}

// ---------------- K7 fused: out = LN2(gelu(h@W1^T+b1)@W2^T + b2 + h) --------
// t never leaves registers; phase-2 A fragments are rebuilt via quad shuffles.
#define S7 136                                // stride%32==8 -> conflict-free LDS
__global__ void __launch_bounds__(256) k7_fused(
        float* __restrict__ out,
        const float* __restrict__ W1, const float* __restrict__ B1,
        const float* __restrict__ W2, const float* __restrict__ B2,
        const float* __restrict__ g2, const float* __restrict__ b2ln) {
    __shared__ float sW[128 * S6];            // 9216 floats; also holds 64*S7=8704
    int tid = threadIdx.x;
    // phase-1 weights: W1[j][k] -> sW[k*S7 + j]
    for (int i = tid; i < 8192; i += 256) {
        int j = i >> 6, k = i & 63;
        sW[k * S7 + j] = W1[i];
    }
    __syncthreads();
    int wid = tid >> 5, lane = tid & 31;
    int gid = lane >> 2, tig = lane & 3;
    int strip = blockIdx.x * 8 + wid;
    if (strip >= NSTRIPS) strip = NSTRIPS - 1;    // clamp: duplicate identical work
    int r0 = strip * 16 + gid, r1 = r0 + 8;

    // ---- phase 1: t = gelu(h @ W1^T + b1), t stays in registers ----
    float t[16][4];
    #pragma unroll
    for (int nt = 0; nt < 16; nt++)
        t[nt][0] = t[nt][1] = t[nt][2] = t[nt][3] = 0.f;

    #pragma unroll 2
    for (int kk = 0; kk < 8; kk++) {
        int kb = kk * 8;
        float a00 = g_h[r0 * D + kb + tig];
        float a10 = g_h[r1 * D + kb + tig];
        float a01 = g_h[r0 * D + kb + tig + 4];
        float a11 = g_h[r1 * D + kb + tig + 4];
        unsigned ah0 = f2tf(a00), ah1 = f2tf(a10), ah2 = f2tf(a01), ah3 = f2tf(a11);
        unsigned al0 = f2tf(a00 - __uint_as_float(ah0));
        unsigned al1 = f2tf(a10 - __uint_as_float(ah1));
        unsigned al2 = f2tf(a01 - __uint_as_float(ah2));
        unsigned al3 = f2tf(a11 - __uint_as_float(ah3));
        const float* br0 = &sW[(kb + tig) * S7];
        const float* br1 = &sW[(kb + tig + 4) * S7];
        #pragma unroll
        for (int nt = 0; nt < 16; nt++) {
            float b0w = br0[nt * 8 + gid];
            float b1w = br1[nt * 8 + gid];
            mma3(t[nt], ah0, ah1, ah2, ah3, al0, al1, al2, al3, b0w, b1w);
        }
    }
    #pragma unroll
    for (int nt = 0; nt < 16; nt++) {
        int col = nt * 8 + 2 * tig;
        float2 bb = *reinterpret_cast<const float2*>(B1 + col);
        t[nt][0] = gelu_exact(t[nt][0] + bb.x);
        t[nt][1] = gelu_exact(t[nt][1] + bb.y);
        t[nt][2] = gelu_exact(t[nt][2] + bb.x);
        t[nt][3] = gelu_exact(t[nt][3] + bb.y);
    }

    // ---- swap weights: W2[n][k] -> sW[k*S6 + n] ----
    __syncthreads();
    for (int i = tid; i < 8192; i += 256) {
        int n = i >> 7, k = i & 127;
        sW[k * S6 + n] = W2[n * 128 + k];
    }
    __syncthreads();

    // ---- phase 2: c = t @ W2^T, A fragments via quad shuffles ----
    float c[8][4];
    #pragma unroll
    for (int nt = 0; nt < 8; nt++)
        c[nt][0] = c[nt][1] = c[nt][2] = c[nt][3] = 0.f;

    int src0 = (lane & ~3) | (tig >> 1);      // owner of col 8kk+tig
    int src1 = src0 + 2;                      // owner of col 8kk+tig+4
    bool odd = (tig & 1);
    #pragma unroll
    for (int kk = 0; kk < 16; kk++) {
        float s00 = __shfl_sync(FULLM, t[kk][0], src0);
        float s01 = __shfl_sync(FULLM, t[kk][1], src0);
        float s02 = __shfl_sync(FULLM, t[kk][2], src0);
        float s03 = __shfl_sync(FULLM, t[kk][3], src0);
        float s10 = __shfl_sync(FULLM, t[kk][0], src1);
        float s11 = __shfl_sync(FULLM, t[kk][1], src1);
        float s12 = __shfl_sync(FULLM, t[kk][2], src1);
        float s13 = __shfl_sync(FULLM, t[kk][3], src1);
        float a00 = odd ? s01 : s00;          // (r0, 8kk+tig)
        float a10 = odd ? s03 : s02;          // (r1, 8kk+tig)
        float a01 = odd ? s11 : s10;          // (r0, 8kk+tig+4)
        float a11 = odd ? s13 : s12;          // (r1, 8kk+tig+4)
        unsigned ah0 = f2tf(a00), ah1 = f2tf(a10), ah2 = f2tf(a01), ah3 = f2tf(a11);
        unsigned al0 = f2tf(a00 - __uint_as_float(ah0));
        unsigned al1 = f2tf(a10 - __uint_as_float(ah1));
        unsigned al2 = f2tf(a01 - __uint_as_float(ah2));
        unsigned al3 = f2tf(a11 - __uint_as_float(ah3));
        int kb = kk * 8;
        const float* br0 = &sW[(kb + tig) * S6];
        const float* br1 = &sW[(kb + tig + 4) * S6];
        #pragma unroll
        for (int nt = 0; nt < 8; nt++) {
            float b0w = br0[nt * 8 + gid];
            float b1w = br1[nt * 8 + gid];
            mma3(c[nt], ah0, ah1, ah2, ah3, al0, al1, al2, al3, b0w, b1w);
        }
    }

    // ---- epilogue: bias + residual + LN2 ----
    float s0 = 0.f, q0 = 0.f, s1 = 0.f, q1 = 0.f;
    #pragma unroll
    for (int nt = 0; nt < 8; nt++) {
        int col = nt * 8 + 2 * tig;
        float2 bb = *reinterpret_cast<const float2*>(B2 + col);
        float2 h0 = *reinterpret_cast<const float2*>(g_h + r0 * D + col);
        float2 h1 = *reinterpret_cast<const float2*>(g_h + r1 * D + col);
        c[nt][0] += bb.x + h0.x;
        c[nt][1] += bb.y + h0.y;
        c[nt][2] += bb.x + h1.x;
        c[nt][3] += bb.y + h1.y;
        s0 += c[nt][0] + c[nt][1]; q0 += c[nt][0] * c[nt][0] + c[nt][1] * c[nt][1];
        s1 += c[nt][2] + c[nt][3]; q1 += c[nt][2] * c[nt][2] + c[nt][3] * c[nt][3];
    }
    #pragma unroll
    for (int o = 1; o <= 2; o <<= 1) {
        s0 += __shfl_xor_sync(FULLM, s0, o);
        q0 += __shfl_xor_sync(FULLM, q0, o);
        s1 += __shfl_xor_sync(FULLM, s1, o);
        q1 += __shfl_xor_sync(FULLM, q1, o);
    }
    float mu0 = s0 * (1.0f / 64.0f), var0 = q0 * (1.0f / 64.0f) - mu0 * mu0;
    float mu1 = s1 * (1.0f / 64.0f), var1 = q1 * (1.0f / 64.0f) - mu1 * mu1;
    float rs0 = rsqrtf(var0 + 1e-5f), rs1 = rsqrtf(var1 + 1e-5f);
    #pragma unroll
    for (int nt = 0; nt < 8; nt++) {
        int col = nt * 8 + 2 * tig;
        float2 gg = *reinterpret_cast<const float2*>(g2 + col);
        float2 bb = *reinterpret_cast<const float2*>(b2ln + col);
        float2 o0 = make_float2((c[nt][0] - mu0) * rs0 * gg.x + bb.x,
                                (c[nt][1] - mu0) * rs0 * gg.y + bb.y);
        float2 o1 = make_float2((c[nt][2] - mu1) * rs1 * gg.x + bb.x,
                                (c[nt][3] - mu1) * rs1 * gg.y + bb.y);
        *reinterpret_cast<float2*>(out + r0 * D + col) = o0;
        *reinterpret_cast<float2*>(out + r1 * D + col) = o1;
    }
}

// ---------------- launcher --------------------------------------------------
extern "C" void kernel_launch(void* const* d_in, const int* in_sizes, int n_in,
                              void* d_out, int out_size) {
    (void)in_sizes; (void)n_in; (void)out_size;
    const float* x    = (const float*)d_in[0];
    const int*   ei   = (const int*)  d_in[1];
    const float* rf   = (const float*)d_in[2];
    const float* Wp   = (const float*)d_in[3];
    const float* Wn   = (const float*)d_in[4];
    const float* attw = (const float*)d_in[5];
    const float* cf   = (const float*)d_in[6];
    const float* W1   = (const float*)d_in[7];
    const float* B1   = (const float*)d_in[8];
    const float* W2   = (const float*)d_in[9];
    const float* B2   = (const float*)d_in[10];
    const float* g1   = (const float*)d_in[11];
    const float* b1   = (const float*)d_in[12];
    const float* g2   = (const float*)d_in[13];
    const float* b2   = (const float*)d_in[14];
    float* out = (float*)d_out;

    const int GBLK = (NSTRIPS + 7) / 8;      // 782

    k12_prep<<<N_NODES / 8, 256>>>(x, attw, ei);
    k3_scan<<<1, 1024>>>();
    k4_scatter<<<N_EDGES / 256, 256>>>(ei, rf);
    k5_agg<<<N_NODES / 8, 256>>>(x, cf);
    k6_gemm_ln1<<<GBLK, 256>>>(x, Wp, Wn, g1, b1);
    k7_fused<<<GBLK, 256>>>(out, W1, B1, W2, B2, g2, b2);
}

// round 10
// speedup vs baseline: 1.7906x; 1.1375x over previous
#include <cuda_runtime.h>
#include <cuda_bf16.h>
#include <math.h>

#define N_NODES 100000
#define N_EDGES 1600000
#define D 64
#define NSTRIPS 6250            // 100000 / 16
#define FULLM 0xffffffffu

// ---------------- scratch (static device globals; no allocations) ----------
__device__ float  g_a1[N_NODES];
__device__ float  g_a2[N_NODES];
__device__ int    g_cnt[N_NODES];       // starts zeroed; re-zeroed by k5 each pass
__device__ int    g_off[N_NODES];
__device__ int    g_cur[N_NODES];
__device__ float4 g_csr[N_EDGES];       // (src_as_int, rf, score, pad)
__device__ float  g_agg[N_NODES * 128]; // cols 0..63: s1-weighted, 64..127: s2-weighted
__device__ float  g_h[N_NODES * D];

__device__ __forceinline__ float gelu_exact(float v) {
    return 0.5f * v * (1.0f + erff(v * 0.70710678118654752440f));
}

// split (x,y) into packed bf16x2 hi and lo (residual) pairs
__device__ __forceinline__ void split2(float x, float y, unsigned &hi, unsigned &lo) {
    __nv_bfloat16 hx = __float2bfloat16_rn(x);
    __nv_bfloat16 hy = __float2bfloat16_rn(y);
    float rx = x - __bfloat162float(hx);
    float ry = y - __bfloat162float(hy);
    __nv_bfloat162 h; h.x = hx; h.y = hy;
    __nv_bfloat162 l; l.x = __float2bfloat16_rn(rx); l.y = __float2bfloat16_rn(ry);
    hi = *reinterpret_cast<unsigned*>(&h);
    lo = *reinterpret_cast<unsigned*>(&l);
}

__device__ __forceinline__ void mma_bf16(float c[4],
                                         unsigned a0, unsigned a1, unsigned a2, unsigned a3,
                                         unsigned b0, unsigned b1) {
    asm("mma.sync.aligned.m16n8k16.row.col.f32.bf16.bf16.f32 "
        "{%0,%1,%2,%3},{%4,%5,%6,%7},{%8,%9},{%0,%1,%2,%3};"
        : "+f"(c[0]), "+f"(c[1]), "+f"(c[2]), "+f"(c[3])
        : "r"(a0), "r"(a1), "r"(a2), "r"(a3), "r"(b0), "r"(b1));
}

// 3-term bf16 split accumulate: c += A*B, error ~|al||bl| ~ 4e-6 rel
__device__ __forceinline__ void mma3b(float c[4],
                                      unsigned ah0, unsigned ah1, unsigned ah2, unsigned ah3,
                                      unsigned al0, unsigned al1, unsigned al2, unsigned al3,
                                      unsigned b0h, unsigned b1h, unsigned b0l, unsigned b1l) {
    mma_bf16(c, ah0, ah1, ah2, ah3, b0h, b1h);
    mma_bf16(c, ah0, ah1, ah2, ah3, b0l, b1l);
    mma_bf16(c, al0, al1, al2, al3, b0h, b1h);
}

// ---------------- K12: per-node attention dots + edge histogram (merged) ----
__global__ void k12_prep(const float* __restrict__ x, const float* __restrict__ attw,
                         const int* __restrict__ ei) {
    int gt = blockIdx.x * blockDim.x + threadIdx.x;
    if (gt < N_EDGES) atomicAdd(&g_cnt[ei[N_EDGES + gt]], 1);
    int w = gt >> 5;
    int l = gt & 31;
    if (w >= N_NODES) return;
    const float* xr = x + w * D;
    float v0 = xr[l], v1 = xr[l + 32];
    float s1 = v0 * attw[l]     + v1 * attw[l + 32];
    float s2 = v0 * attw[D + l] + v1 * attw[D + l + 32];
    #pragma unroll
    for (int o = 16; o; o >>= 1) {
        s1 += __shfl_xor_sync(FULLM, s1, o);
        s2 += __shfl_xor_sync(FULLM, s2, o);
    }
    if (l == 0) { g_a1[w] = s1; g_a2[w] = s2; }
}

// ---------------- K3: tiled coalesced single-block scan ---------------------
__global__ void k3_scan() {
    __shared__ int wsum[32];
    int t = threadIdx.x, lane = t & 31, wid = t >> 5;
    int base = 0;
    for (int tile = 0; tile < N_NODES; tile += 1024) {
        int idx = tile + t;
        int v = (idx < N_NODES) ? g_cnt[idx] : 0;
        int inc = v;
        #pragma unroll
        for (int o = 1; o < 32; o <<= 1) {
            int u = __shfl_up_sync(FULLM, inc, o);
            if (lane >= o) inc += u;
        }
        if (lane == 31) wsum[wid] = inc;
        __syncthreads();
        if (wid == 0) {
            int ws = wsum[lane];
            int winc = ws;
            #pragma unroll
            for (int o = 1; o < 32; o <<= 1) {
                int u = __shfl_up_sync(FULLM, winc, o);
                if (lane >= o) winc += u;
            }
            wsum[lane] = winc;
        }
        __syncthreads();
        int excl = base + inc - v + (wid ? wsum[wid - 1] : 0);
        if (idx < N_NODES) { g_off[idx] = excl; g_cur[idx] = excl; }
        base += wsum[31];
        __syncthreads();
    }
}

// ---------------- K4: scatter edges into CSR (packed float4) ----------------
__global__ void k4_scatter(const int* __restrict__ ei, const float* __restrict__ rf) {
    int e = blockIdx.x * blockDim.x + threadIdx.x;
    if (e >= N_EDGES) return;
    int s = ei[e], d = ei[N_EDGES + e];
    int pos = atomicAdd(&g_cur[d], 1);
    g_csr[pos] = make_float4(__int_as_float(s), rf[e], g_a1[s] + g_a2[d], 0.0f);
}

// ---------------- K5: warp-per-node softmax + half-warp float4 gather -------
__global__ void k5_agg(const float* __restrict__ x, const float* __restrict__ cf) {
    int w = (blockIdx.x * blockDim.x + threadIdx.x) >> 5;
    int l = threadIdx.x & 31;
    if (w >= N_NODES) return;
    int beg = g_off[w], cnt = g_cnt[w];
    float alpha = 1.0f / (1.0f + __expf(-cf[0]));

    float4 ed = make_float4(0.f, 0.f, -1e30f, 0.f);
    if (l < cnt) ed = g_csr[beg + l];

    float m = ed.z;
    for (int i = 32 + l; i < cnt; i += 32) m = fmaxf(m, g_csr[beg + i].z);
    #pragma unroll
    for (int o = 16; o; o >>= 1) m = fmaxf(m, __shfl_xor_sync(FULLM, m, o));

    float e0 = (l < cnt) ? __expf(ed.z - m) : 0.f;
    float den = e0;
    for (int i = 32 + l; i < cnt; i += 32) den += __expf(g_csr[beg + i].z - m);
    #pragma unroll
    for (int o = 16; o; o >>= 1) den += __shfl_xor_sync(FULLM, den, o);
    float inv = (cnt > 0) ? (1.0f / den) : 0.f;

    float w1 = e0 * inv * alpha * ed.y;
    float w2 = e0 * inv * (1.0f - alpha);
    int   sr = __float_as_int(ed.x);

    int h = l >> 4, j = l & 15;
    float4 a1 = make_float4(0.f, 0.f, 0.f, 0.f);
    float4 a2 = make_float4(0.f, 0.f, 0.f, 0.f);

    int n0  = cnt < 32 ? cnt : 32;
    int n0e = (n0 + 1) & ~1;
    int i = 0;
    for (; i + 8 <= n0e; i += 8) {
        #pragma unroll
        for (int b = 0; b < 4; b++) {
            int   e  = i + 2 * b + h;
            int   se = __shfl_sync(FULLM, sr, e);
            float p  = __shfl_sync(FULLM, w1, e);
            float q  = __shfl_sync(FULLM, w2, e);
            float4 v = *reinterpret_cast<const float4*>(x + se * D + 4 * j);
            a1.x += p * v.x; a1.y += p * v.y; a1.z += p * v.z; a1.w += p * v.w;
            a2.x += q * v.x; a2.y += q * v.y; a2.z += q * v.z; a2.w += q * v.w;
        }
    }
    for (; i < n0e; i += 2) {
        int   e  = i + h;
        int   se = __shfl_sync(FULLM, sr, e);
        float p  = __shfl_sync(FULLM, w1, e);
        float q  = __shfl_sync(FULLM, w2, e);
        float4 v = *reinterpret_cast<const float4*>(x + se * D + 4 * j);
        a1.x += p * v.x; a1.y += p * v.y; a1.z += p * v.z; a1.w += p * v.w;
        a2.x += q * v.x; a2.y += q * v.y; a2.z += q * v.z; a2.w += q * v.w;
    }
    for (int base2 = 32; base2 < cnt; base2 += 32) {
        int k = base2 + l;
        float4 e2 = make_float4(0.f, 0.f, 0.f, 0.f);
        float ew = 0.f;
        if (k < cnt) { e2 = g_csr[beg + k]; ew = __expf(e2.z - m) * inv; }
        float u1 = ew * alpha * e2.y;
        float u2 = ew * (1.0f - alpha);
        int  s2r = __float_as_int(e2.x);
        int lim = cnt - base2; if (lim > 32) lim = 32;
        int lime = (lim + 1) & ~1;
        for (int ii = 0; ii < lime; ii += 2) {
            int   e  = ii + h;
            int   se = __shfl_sync(FULLM, s2r, e);
            float p  = __shfl_sync(FULLM, u1, e);
            float q  = __shfl_sync(FULLM, u2, e);
            float4 v = *reinterpret_cast<const float4*>(x + se * D + 4 * j);
            a1.x += p * v.x; a1.y += p * v.y; a1.z += p * v.z; a1.w += p * v.w;
            a2.x += q * v.x; a2.y += q * v.y; a2.z += q * v.z; a2.w += q * v.w;
        }
    }
    a1.x += __shfl_xor_sync(FULLM, a1.x, 16);
    a1.y += __shfl_xor_sync(FULLM, a1.y, 16);
    a1.z += __shfl_xor_sync(FULLM, a1.z, 16);
    a1.w += __shfl_xor_sync(FULLM, a1.w, 16);
    a2.x += __shfl_xor_sync(FULLM, a2.x, 16);
    a2.y += __shfl_xor_sync(FULLM, a2.y, 16);
    a2.z += __shfl_xor_sync(FULLM, a2.z, 16);
    a2.w += __shfl_xor_sync(FULLM, a2.w, 16);
    float4 sel = h ? a2 : a1;
    *reinterpret_cast<float4*>(g_agg + w * 128 + 4 * l) = sel;
    if (l == 0) g_cnt[w] = 0;
}

// ---------------- K6: h = LN1(gelu(agg @ [Wp;Wn]^T) + x)  (bf16x3 MMA) ------
#define SN6 72                      // n-stride: (72*tig+gid)%32 = 8tig+gid, injective
__global__ void __launch_bounds__(256) k6_gemm_ln1(
        const float* __restrict__ x,
        const float* __restrict__ Wp, const float* __restrict__ Wn,
        const float* __restrict__ g1, const float* __restrict__ b1) {
    __shared__ unsigned sH[64 * SN6];       // B hi pairs: [kp][n], kp=k/2 (k<128)
    __shared__ unsigned sL[64 * SN6];       // B lo pairs
    int tid = threadIdx.x;
    for (int i = tid; i < 4096; i += 256) {
        int kp = i >> 6, n = i & 63;
        float2 wv = (kp < 32)
            ? *reinterpret_cast<const float2*>(Wp + n * 64 + 2 * kp)
            : *reinterpret_cast<const float2*>(Wn + n * 64 + 2 * (kp - 32));
        unsigned h, l;
        split2(wv.x, wv.y, h, l);
        sH[kp * SN6 + n] = h;
        sL[kp * SN6 + n] = l;
    }
    __syncthreads();
    int wid = tid >> 5, lane = tid & 31;
    int gid = lane >> 2, tig = lane & 3;
    int strip = blockIdx.x * 8 + wid;
    if (strip >= NSTRIPS) return;
    int r0 = strip * 16 + gid, r1 = r0 + 8;

    float c[8][4];
    #pragma unroll
    for (int nt = 0; nt < 8; nt++)
        c[nt][0] = c[nt][1] = c[nt][2] = c[nt][3] = 0.f;

    #pragma unroll 2
    for (int kk = 0; kk < 8; kk++) {           // K=16 per iteration
        int kb = kk * 16, kp0 = kk * 8;
        float2 A0 = *reinterpret_cast<const float2*>(g_agg + r0 * 128 + kb + 2 * tig);
        float2 A1 = *reinterpret_cast<const float2*>(g_agg + r1 * 128 + kb + 2 * tig);
        float2 A2 = *reinterpret_cast<const float2*>(g_agg + r0 * 128 + kb + 2 * tig + 8);
        float2 A3 = *reinterpret_cast<const float2*>(g_agg + r1 * 128 + kb + 2 * tig + 8);
        unsigned ah0, al0, ah1, al1, ah2, al2, ah3, al3;
        split2(A0.x, A0.y, ah0, al0);
        split2(A1.x, A1.y, ah1, al1);
        split2(A2.x, A2.y, ah2, al2);
        split2(A3.x, A3.y, ah3, al3);
        const unsigned* rh0 = &sH[(kp0 + tig) * SN6];
        const unsigned* rh1 = &sH[(kp0 + tig + 4) * SN6];
        const unsigned* rl0 = &sL[(kp0 + tig) * SN6];
        const unsigned* rl1 = &sL[(kp0 + tig + 4) * SN6];
        #pragma unroll
        for (int nt = 0; nt < 8; nt++) {
            int bi = nt * 8 + gid;
            mma3b(c[nt], ah0, ah1, ah2, ah3, al0, al1, al2, al3,
                  rh0[bi], rh1[bi], rl0[bi], rl1[bi]);
        }
    }
    float s0 = 0.f, q0 = 0.f, s1 = 0.f, q1 = 0.f;
    #pragma unroll
    for (int nt = 0; nt < 8; nt++) {
        int col = nt * 8 + 2 * tig;
        float2 xv0 = *reinterpret_cast<const float2*>(x + r0 * D + col);
        float2 xv1 = *reinterpret_cast<const float2*>(x + r1 * D + col);
        c[nt][0] = gelu_exact(c[nt][0]) + xv0.x;
        c[nt][1] = gelu_exact(c[nt][1]) + xv0.y;
        c[nt][2] = gelu_exact(c[nt][2]) + xv1.x;
        c[nt][3] = gelu_exact(c[nt][3]) + xv1.y;
        s0 += c[nt][0] + c[nt][1]; q0 += c[nt][0] * c[nt][0] + c[nt][1] * c[nt][1];
        s1 += c[nt][2] + c[nt][3]; q1 += c[nt][2] * c[nt][2] + c[nt][3] * c[nt][3];
    }
    #pragma unroll
    for (int o = 1; o <= 2; o <<= 1) {
        s0 += __shfl_xor_sync(FULLM, s0, o);
        q0 += __shfl_xor_sync(FULLM, q0, o);
        s1 += __shfl_xor_sync(FULLM, s1, o);
        q1 += __shfl_xor_sync(FULLM, q1, o);
    }
    float mu0 = s0 * (1.0f / 64.0f), var0 = q0 * (1.0f / 64.0f) - mu0 * mu0;
    float mu1 = s1 * (1.0f / 64.0f), var1 = q1 * (1.0f / 64.0f) - mu1 * mu1;
    float rs0 = rsqrtf(var0 + 1e-5f), rs1 = rsqrtf(var1 + 1e-5f);
    #pragma unroll
    for (int nt = 0; nt < 8; nt++) {
        int col = nt * 8 + 2 * tig;
        float2 gg = *reinterpret_cast<const float2*>(g1 + col);
        float2 bb = *reinterpret_cast<const float2*>(b1 + col);
        float2 o0 = make_float2((c[nt][0] - mu0) * rs0 * gg.x + bb.x,
                                (c[nt][1] - mu0) * rs0 * gg.y + bb.y);
        float2 o1 = make_float2((c[nt][2] - mu1) * rs1 * gg.x + bb.x,
                                (c[nt][3] - mu1) * rs1 * gg.y + bb.y);
        *reinterpret_cast<float2*>(g_h + r0 * D + col) = o0;
        *reinterpret_cast<float2*>(g_h + r1 * D + col) = o1;
    }
}

// ---------------- K7 fused: out = LN2(gelu(h@W1^T+b1)@W2^T + b2 + h) --------
// t stays in registers; with k16 pairs the phase-2 A fragments ARE the
// phase-1 C fragments (same (gid,2*tig) mapping) — no shuffles needed.
#define SN7 136
__global__ void __launch_bounds__(256) k7_fused(
        float* __restrict__ out,
        const float* __restrict__ W1, const float* __restrict__ B1,
        const float* __restrict__ W2, const float* __restrict__ B2,
        const float* __restrict__ g2, const float* __restrict__ b2ln) {
    __shared__ unsigned sH[64 * SN6];        // 4608 >= 32*136=4352 (phase1)
    __shared__ unsigned sL[64 * SN6];
    int tid = threadIdx.x;
    // phase-1 weights: W1 [128][64] -> pairs [kp<32][j<128]
    for (int i = tid; i < 4096; i += 256) {
        int kp = i >> 7, j = i & 127;
        float2 wv = *reinterpret_cast<const float2*>(W1 + j * 64 + 2 * kp);
        unsigned h, l;
        split2(wv.x, wv.y, h, l);
        sH[kp * SN7 + j] = h;
        sL[kp * SN7 + j] = l;
    }
    __syncthreads();
    int wid = tid >> 5, lane = tid & 31;
    int gid = lane >> 2, tig = lane & 3;
    int strip = blockIdx.x * 8 + wid;
    if (strip >= NSTRIPS) strip = NSTRIPS - 1;    // clamp: duplicate identical work
    int r0 = strip * 16 + gid, r1 = r0 + 8;

    // ---- phase 1: t = gelu(h @ W1^T + b1) ----
    float t[16][4];
    #pragma unroll
    for (int nt = 0; nt < 16; nt++)
        t[nt][0] = t[nt][1] = t[nt][2] = t[nt][3] = 0.f;

    #pragma unroll
    for (int kk = 0; kk < 4; kk++) {
        int kb = kk * 16, kp0 = kk * 8;
        float2 A0 = *reinterpret_cast<const float2*>(g_h + r0 * D + kb + 2 * tig);
        float2 A1 = *reinterpret_cast<const float2*>(g_h + r1 * D + kb + 2 * tig);
        float2 A2 = *reinterpret_cast<const float2*>(g_h + r0 * D + kb + 2 * tig + 8);
        float2 A3 = *reinterpret_cast<const float2*>(g_h + r1 * D + kb + 2 * tig + 8);
        unsigned ah0, al0, ah1, al1, ah2, al2, ah3, al3;
        split2(A0.x, A0.y, ah0, al0);
        split2(A1.x, A1.y, ah1, al1);
        split2(A2.x, A2.y, ah2, al2);
        split2(A3.x, A3.y, ah3, al3);
        const unsigned* rh0 = &sH[(kp0 + tig) * SN7];
        const unsigned* rh1 = &sH[(kp0 + tig + 4) * SN7];
        const unsigned* rl0 = &sL[(kp0 + tig) * SN7];
        const unsigned* rl1 = &sL[(kp0 + tig + 4) * SN7];
        #pragma unroll
        for (int nt = 0; nt < 16; nt++) {
            int bi = nt * 8 + gid;
            mma3b(t[nt], ah0, ah1, ah2, ah3, al0, al1, al2, al3,
                  rh0[bi], rh1[bi], rl0[bi], rl1[bi]);
        }
    }
    #pragma unroll
    for (int nt = 0; nt < 16; nt++) {
        int col = nt * 8 + 2 * tig;
        float2 bb = *reinterpret_cast<const float2*>(B1 + col);
        t[nt][0] = gelu_exact(t[nt][0] + bb.x);
        t[nt][1] = gelu_exact(t[nt][1] + bb.y);
        t[nt][2] = gelu_exact(t[nt][2] + bb.x);
        t[nt][3] = gelu_exact(t[nt][3] + bb.y);
    }

    // ---- swap weights: W2 [64][128] -> pairs [kp<64][n<64] ----
    __syncthreads();
    for (int i = tid; i < 4096; i += 256) {
        int kp = i >> 6, n = i & 63;
        float2 wv = *reinterpret_cast<const float2*>(W2 + n * 128 + 2 * kp);
        unsigned h, l;
        split2(wv.x, wv.y, h, l);
        sH[kp * SN6 + n] = h;
        sL[kp * SN6 + n] = l;
    }
    __syncthreads();

    // ---- phase 2: c = t @ W2^T (A fragments direct from t registers) ----
    float c[8][4];
    #pragma unroll
    for (int nt = 0; nt < 8; nt++)
        c[nt][0] = c[nt][1] = c[nt][2] = c[nt][3] = 0.f;

    #pragma unroll
    for (int kk = 0; kk < 8; kk++) {
        int kp0 = kk * 8;
        unsigned ah0, al0, ah1, al1, ah2, al2, ah3, al3;
        split2(t[2 * kk][0],     t[2 * kk][1],     ah0, al0);   // (r0, kb+2t..)
        split2(t[2 * kk][2],     t[2 * kk][3],     ah1, al1);   // (r1, kb+2t..)
        split2(t[2 * kk + 1][0], t[2 * kk + 1][1], ah2, al2);   // (r0, kb+2t+8..)
        split2(t[2 * kk + 1][2], t[2 * kk + 1][3], ah3, al3);   // (r1, kb+2t+8..)
        const unsigned* rh0 = &sH[(kp0 + tig) * SN6];
        const unsigned* rh1 = &sH[(kp0 + tig + 4) * SN6];
        const unsigned* rl0 = &sL[(kp0 + tig) * SN6];
        const unsigned* rl1 = &sL[(kp0 + tig + 4) * SN6];
        #pragma unroll
        for (int nt = 0; nt < 8; nt++) {
            int bi = nt * 8 + gid;
            mma3b(c[nt], ah0, ah1, ah2, ah3, al0, al1, al2, al3,
                  rh0[bi], rh1[bi], rl0[bi], rl1[bi]);
        }
    }

    // ---- epilogue: bias + residual + LN2 ----
    float s0 = 0.f, q0 = 0.f, s1 = 0.f, q1 = 0.f;
    #pragma unroll
    for (int nt = 0; nt < 8; nt++) {
        int col = nt * 8 + 2 * tig;
        float2 bb = *reinterpret_cast<const float2*>(B2 + col);
        float2 h0 = *reinterpret_cast<const float2*>(g_h + r0 * D + col);
        float2 h1 = *reinterpret_cast<const float2*>(g_h + r1 * D + col);
        c[nt][0] += bb.x + h0.x;
        c[nt][1] += bb.y + h0.y;
        c[nt][2] += bb.x + h1.x;
        c[nt][3] += bb.y + h1.y;
        s0 += c[nt][0] + c[nt][1]; q0 += c[nt][0] * c[nt][0] + c[nt][1] * c[nt][1];
        s1 += c[nt][2] + c[nt][3]; q1 += c[nt][2] * c[nt][2] + c[nt][3] * c[nt][3];
    }
    #pragma unroll
    for (int o = 1; o <= 2; o <<= 1) {
        s0 += __shfl_xor_sync(FULLM, s0, o);
        q0 += __shfl_xor_sync(FULLM, q0, o);
        s1 += __shfl_xor_sync(FULLM, s1, o);
        q1 += __shfl_xor_sync(FULLM, q1, o);
    }
    float mu0 = s0 * (1.0f / 64.0f), var0 = q0 * (1.0f / 64.0f) - mu0 * mu0;
    float mu1 = s1 * (1.0f / 64.0f), var1 = q1 * (1.0f / 64.0f) - mu1 * mu1;
    float rs0 = rsqrtf(var0 + 1e-5f), rs1 = rsqrtf(var1 + 1e-5f);
    #pragma unroll
    for (int nt = 0; nt < 8; nt++) {
        int col = nt * 8 + 2 * tig;
        float2 gg = *reinterpret_cast<const float2*>(g2 + col);
        float2 bb = *reinterpret_cast<const float2*>(b2ln + col);
        float2 o0 = make_float2((c[nt][0] - mu0) * rs0 * gg.x + bb.x,
                                (c[nt][1] - mu0) * rs0 * gg.y + bb.y);
        float2 o1 = make_float2((c[nt][2] - mu1) * rs1 * gg.x + bb.x,
                                (c[nt][3] - mu1) * rs1 * gg.y + bb.y);
        *reinterpret_cast<float2*>(out + r0 * D + col) = o0;
        *reinterpret_cast<float2*>(out + r1 * D + col) = o1;
    }
}

// ---------------- launcher --------------------------------------------------
extern "C" void kernel_launch(void* const* d_in, const int* in_sizes, int n_in,
                              void* d_out, int out_size) {
    (void)in_sizes; (void)n_in; (void)out_size;
    const float* x    = (const float*)d_in[0];
    const int*   ei   = (const int*)  d_in[1];
    const float* rf   = (const float*)d_in[2];
    const float* Wp   = (const float*)d_in[3];
    const float* Wn   = (const float*)d_in[4];
    const float* attw = (const float*)d_in[5];
    const float* cf   = (const float*)d_in[6];
    const float* W1   = (const float*)d_in[7];
    const float* B1   = (const float*)d_in[8];
    const float* W2   = (const float*)d_in[9];
    const float* B2   = (const float*)d_in[10];
    const float* g1   = (const float*)d_in[11];
    const float* b1   = (const float*)d_in[12];
    const float* g2   = (const float*)d_in[13];
    const float* b2   = (const float*)d_in[14];
    float* out = (float*)d_out;

    const int GBLK = (NSTRIPS + 7) / 8;      // 782

    k12_prep<<<N_NODES / 8, 256>>>(x, attw, ei);
    k3_scan<<<1, 1024>>>();
    k4_scatter<<<N_EDGES / 256, 256>>>(ei, rf);
    k5_agg<<<N_NODES / 8, 256>>>(x, cf);
    k6_gemm_ln1<<<GBLK, 256>>>(x, Wp, Wn, g1, b1);
    k7_fused<<<GBLK, 256>>>(out, W1, B1, W2, B2, g2, b2);
}